// round 15
// baseline (speedup 1.0000x reference)
#include <cuda_runtime.h>
#include <cuda_bf16.h>
#include <math.h>

// Problem constants
#define Bb 2
#define LL 2048
#define DD 256
#define KK 32
#define FF 64          // 2*K feature dim
#define MM (Bb*LL)     // 4096 rows
#define CC 128         // chunk size
#define NC (LL/CC)     // 16 chunks per batch
#define PI_F 3.14159265358979323846f

// ---------------- scratch (device globals; no allocation allowed) ----------------
__device__ float g_hk[MM*DD];
__device__ float g_hq[MM*DD];
__device__ float g_vc[MM*DD];
__device__ float g_vp[MM*DD];
__device__ float g_g1[MM*64];
__device__ float g_kf[MM*FF];
__device__ float g_qf[MM*FF];
__device__ float g_gates[MM*2];
__device__ float g_S[Bb*NC*FF*DD];         // per-chunk content state sums (mma)
__device__ float g_P[Bb*NC*FF*DD];         // chunk-level exclusive prefix of states
__device__ float g_psnap[Bb*64*4*2*DD];    // pos accum snapshots every 8 rows (inclusive)
__device__ float g_pprefix[Bb*64*2*DD];    // exclusive prefix at 32-row granularity
__device__ float g_scores[Bb*NC*CC*CC];    // intra-chunk masked scores
__device__ float g_cont[MM*DD];
__device__ float g_norm[MM*DD];
__device__ float g_cph[LL*DD];             // cached cos(base_phases[:LL])
__device__ float g_sph[LL*DD];             // cached sin(base_phases[:LL])

// mma consumes raw f32 bit patterns as tf32 (HW truncates mantissa; no cvt needed)
__device__ __forceinline__ void mma_tf32(float c[4],
    unsigned a0, unsigned a1, unsigned a2, unsigned a3,
    unsigned b0, unsigned b1)
{
    asm volatile(
        "mma.sync.aligned.m16n8k8.row.col.f32.tf32.tf32.f32 "
        "{%0,%1,%2,%3}, {%4,%5,%6,%7}, {%8,%9}, {%0,%1,%2,%3};"
        : "+f"(c[0]), "+f"(c[1]), "+f"(c[2]), "+f"(c[3])
        : "r"(a0), "r"(a1), "r"(a2), "r"(a3), "r"(b0), "r"(b1));
}

// ---------------- cp.async helpers ----------------
__device__ __forceinline__ void cp_async16(void* smem_dst, const void* gsrc) {
    unsigned saddr = (unsigned)__cvta_generic_to_shared(smem_dst);
    asm volatile("cp.async.cg.shared.global [%0], [%1], 16;" :: "r"(saddr), "l"(gsrc));
}
__device__ __forceinline__ void cp_commit() {
    asm volatile("cp.async.commit_group;");
}
__device__ __forceinline__ void cp_wait1() {
    asm volatile("cp.async.wait_group 1;");
}
__device__ __forceinline__ void cp_wait0() {
    asm volatile("cp.async.wait_group 0;");
}

// ================= Kernel 1: fused first-layer GEMMs, 128x128 tiles (3-stage) =========
// grid (32, 9): ct<8 -> [hk|hq|vc|vp] x 2 col-halves; ct==8 -> g1 (64 cols, predicated)
__global__ __launch_bounds__(256) void k1_mma(
    const float* __restrict__ x,
    const float* __restrict__ Wk1, const float* __restrict__ bk1,
    const float* __restrict__ Wq1, const float* __restrict__ bq1,
    const float* __restrict__ Wvc, const float* __restrict__ bvc,
    const float* __restrict__ Wvp, const float* __restrict__ bvp,
    const float* __restrict__ Wg1, const float* __restrict__ bg1)
{
    extern __shared__ __align__(16) float smem[];
    float (*As)[128][20] = (float(*)[128][20])smem;            // 3*2560 floats
    float (*Bs)[16][132] = (float(*)[16][132])(smem + 7680);   // 3*2112 floats
    int ct = blockIdx.y;
    const float* W; const float* bias; float* outp; int Nseg; int act; int colbase;
    if (ct < 8) {
        int seg = ct >> 1;
        colbase = (ct & 1) * 128;
        Nseg = 256;
        if (seg == 0)      { W = Wk1; bias = bk1; outp = g_hk; act = 1; }
        else if (seg == 1) { W = Wq1; bias = bq1; outp = g_hq; act = 1; }
        else if (seg == 2) { W = Wvc; bias = bvc; outp = g_vc; act = 0; }
        else               { W = Wvp; bias = bvp; outp = g_vp; act = 0; }
    } else {
        W = Wg1; bias = bg1; outp = g_g1; Nseg = 64; act = 2; colbase = 0;
    }
    int row0 = blockIdx.x * 128;
    int tid = threadIdx.x;
    int w = tid >> 5, lane = tid & 31;
    int wm = (w & 3) * 32;
    int wn = (w >> 2) * 64;
    int lq = lane >> 2, lr = lane & 3;
    int r0 = tid >> 2, c4 = (tid & 3) * 4;
    int rB = tid >> 5, cB = (tid & 31) * 4;
    bool bok = (colbase + cB) < Nseg;
    float c[2][8][4] = {};

    #pragma unroll
    for (int p = 0; p < 2; p++) {
        int k0 = p * 16;
        cp_async16(&As[p][r0][c4],    &x[(row0 + r0) * 256 + k0 + c4]);
        cp_async16(&As[p][r0+64][c4], &x[(row0 + r0 + 64) * 256 + k0 + c4]);
        if (bok) {
            cp_async16(&Bs[p][rB][cB],   &W[(k0 + rB) * Nseg + colbase + cB]);
            cp_async16(&Bs[p][rB+8][cB], &W[(k0 + rB + 8) * Nseg + colbase + cB]);
        }
        cp_commit();
    }

    for (int s = 0; s < 16; s++) {
        if (s < 15) cp_wait1(); else cp_wait0();
        __syncthreads();
        int cur = s % 3;
        #pragma unroll
        for (int ks = 0; ks < 2; ks++) {
            unsigned a[2][4];
            #pragma unroll
            for (int mt = 0; mt < 2; mt++) {
                int rr = wm + mt*16 + lq;
                int cc = ks*8 + lr;
                a[mt][0] = __float_as_uint(As[cur][rr][cc]);
                a[mt][1] = __float_as_uint(As[cur][rr+8][cc]);
                a[mt][2] = __float_as_uint(As[cur][rr][cc+4]);
                a[mt][3] = __float_as_uint(As[cur][rr+8][cc+4]);
            }
            #pragma unroll
            for (int nt = 0; nt < 8; nt++) {
                int bn = wn + nt*8 + lq;
                unsigned b0 = __float_as_uint(Bs[cur][ks*8+lr][bn]);
                unsigned b1 = __float_as_uint(Bs[cur][ks*8+lr+4][bn]);
                #pragma unroll
                for (int mt = 0; mt < 2; mt++)
                    mma_tf32(c[mt][nt], a[mt][0], a[mt][1], a[mt][2], a[mt][3], b0, b1);
            }
        }
        if (s < 14) {
            int st = (s + 2) % 3;
            int k0 = (s + 2) * 16;
            cp_async16(&As[st][r0][c4],    &x[(row0 + r0) * 256 + k0 + c4]);
            cp_async16(&As[st][r0+64][c4], &x[(row0 + r0 + 64) * 256 + k0 + c4]);
            if (bok) {
                cp_async16(&Bs[st][rB][cB],   &W[(k0 + rB) * Nseg + colbase + cB]);
                cp_async16(&Bs[st][rB+8][cB], &W[(k0 + rB + 8) * Nseg + colbase + cB]);
            }
            cp_commit();
        }
    }
    #pragma unroll
    for (int mt = 0; mt < 2; mt++) {
        #pragma unroll
        for (int nt = 0; nt < 8; nt++) {
            int cc = colbase + wn + nt*8 + lr*2;
            if (cc < Nseg) {
                int r = row0 + wm + mt*16 + lq;
                float b0v = bias[cc], b1v = bias[cc+1];
                float v00 = c[mt][nt][0] + b0v, v01 = c[mt][nt][1] + b1v;
                float v10 = c[mt][nt][2] + b0v, v11 = c[mt][nt][3] + b1v;
                if (act == 1) { v00 = tanhf(v00); v01 = tanhf(v01); v10 = tanhf(v10); v11 = tanhf(v11); }
                else if (act == 2) { v00 = fmaxf(v00,0.f); v01 = fmaxf(v01,0.f); v10 = fmaxf(v10,0.f); v11 = fmaxf(v11,0.f); }
                *(float2*)&outp[r * Nseg + cc] = make_float2(v00, v01);
                *(float2*)&outp[(r+8) * Nseg + cc] = make_float2(v10, v11);
            }
        }
    }
}

// ===== Kernel 2+3b merged: split phase GEMMs (3-stage cp.async) || pos partials =======
// blocks [0,32): k-path GEMM + gates; [32,64): q-path GEMM;
// blocks [64,128): pos partials for BOTH batches (one sincos, cached to g_cph/g_sph).
__global__ __launch_bounds__(256) void k23b_mma(
    const float* __restrict__ Wk2, const float* __restrict__ bk2,
    const float* __restrict__ Wq2, const float* __restrict__ bq2,
    const float* __restrict__ Wg2, const float* __restrict__ bg2,
    const float* __restrict__ base_phases)
{
    __shared__ __align__(16) float As[3][128][20];
    __shared__ __align__(16) float Bs[3][16][36];
    int tid = threadIdx.x;
    int bx = blockIdx.x;

    if (bx >= 64) {
        // ---- pos partial sums for both batches + sincos cache ----
        int s = bx - 64;            // 0..63
        int l0 = s * 32;
        int row0_0 = l0;            // b = 0
        int row0_1 = LL + l0;       // b = 1
        int d = tid;
        float par0 = 0.f, pai0 = 0.f, par1 = 0.f, pai1 = 0.f;
        #pragma unroll
        for (int g = 0; g < 4; g++) {
            float ph8[8], v0[8], v1[8];
            #pragma unroll
            for (int j = 0; j < 8; j++) {
                ph8[j] = base_phases[(l0 + g*8 + j) * 256 + d];
                v0[j] = g_vp[(row0_0 + g*8 + j) * 256 + d];
                v1[j] = g_vp[(row0_1 + g*8 + j) * 256 + d];
            }
            #pragma unroll
            for (int j = 0; j < 8; j++) {
                float sp, cp; __sincosf(ph8[j], &sp, &cp);
                int l = l0 + g*8 + j;
                g_cph[l*256 + d] = cp;
                g_sph[l*256 + d] = sp;
                par0 += v0[j] * cp; pai0 += v0[j] * sp;
                par1 += v1[j] * cp; pai1 += v1[j] * sp;
            }
            int sb0 = (s * 4 + g) * 512;
            int sb1 = ((64 + s) * 4 + g) * 512;
            g_psnap[sb0 + d] = par0; g_psnap[sb0 + 256 + d] = pai0;
            g_psnap[sb1 + d] = par1; g_psnap[sb1 + 256 + d] = pai1;
        }
        return;
    }

    // ---- phase-feature GEMM: one path per block ----
    bool isq = (bx >= 32);
    int row0 = (bx & 31) * 128;
    const float* H  = isq ? g_hq : g_hk;
    const float* W2 = isq ? Wq2 : Wk2;
    const float* bvec = isq ? bq2 : bk2;
    float* fdst = isq ? g_qf : g_kf;

    int w = tid >> 5, lane = tid & 31;
    int wm = (w & 3) * 32;
    int wn = (w >> 2) * 16;
    int lq = lane >> 2, lr = lane & 3;
    int r0 = tid >> 2, c4 = (tid & 3) * 4;
    int brB = tid >> 3, bc4B = (tid & 7) * 4;   // valid for tid < 128
    float c[2][2][4] = {};

    #pragma unroll
    for (int p = 0; p < 2; p++) {
        int k0 = p * 16;
        cp_async16(&As[p][r0][c4],    &H[(row0 + r0) * 256 + k0 + c4]);
        cp_async16(&As[p][r0+64][c4], &H[(row0 + r0 + 64) * 256 + k0 + c4]);
        if (tid < 128)
            cp_async16(&Bs[p][brB][bc4B], &W2[(k0 + brB) * 32 + bc4B]);
        cp_commit();
    }

    for (int s = 0; s < 16; s++) {
        if (s < 15) cp_wait1(); else cp_wait0();
        __syncthreads();
        int cur = s % 3;
        #pragma unroll
        for (int ks = 0; ks < 2; ks++) {
            unsigned a[2][4];
            #pragma unroll
            for (int mt = 0; mt < 2; mt++) {
                int rr = wm + mt*16 + lq;
                int cc = ks*8 + lr;
                a[mt][0] = __float_as_uint(As[cur][rr][cc]);
                a[mt][1] = __float_as_uint(As[cur][rr+8][cc]);
                a[mt][2] = __float_as_uint(As[cur][rr][cc+4]);
                a[mt][3] = __float_as_uint(As[cur][rr+8][cc+4]);
            }
            #pragma unroll
            for (int nt = 0; nt < 2; nt++) {
                int bn = wn + nt*8 + lq;
                unsigned b0 = __float_as_uint(Bs[cur][ks*8+lr][bn]);
                unsigned b1 = __float_as_uint(Bs[cur][ks*8+lr+4][bn]);
                #pragma unroll
                for (int mt = 0; mt < 2; mt++)
                    mma_tf32(c[mt][nt], a[mt][0], a[mt][1], a[mt][2], a[mt][3], b0, b1);
            }
        }
        if (s < 14) {
            int st = (s + 2) % 3;
            int k0 = (s + 2) * 16;
            cp_async16(&As[st][r0][c4],    &H[(row0 + r0) * 256 + k0 + c4]);
            cp_async16(&As[st][r0+64][c4], &H[(row0 + r0 + 64) * 256 + k0 + c4]);
            if (tid < 128)
                cp_async16(&Bs[st][brB][bc4B], &W2[(k0 + brB) * 32 + bc4B]);
            cp_commit();
        }
    }

    #pragma unroll
    for (int mt = 0; mt < 2; mt++) {
        #pragma unroll
        for (int nt = 0; nt < 2; nt++) {
            int r = row0 + wm + mt*16 + lq;
            int cn = wn + nt*8 + lr*2;
            float b0v = bvec[cn], b1v = bvec[cn+1];
            float ph;
            float sp, cp;
            ph = tanhf(c[mt][nt][0] + b0v) * PI_F; __sincosf(ph, &sp, &cp);
            fdst[r*64 + cn] = cp; fdst[r*64 + 32 + cn] = sp;
            ph = tanhf(c[mt][nt][1] + b1v) * PI_F; __sincosf(ph, &sp, &cp);
            fdst[r*64 + cn+1] = cp; fdst[r*64 + 32 + cn+1] = sp;
            ph = tanhf(c[mt][nt][2] + b0v) * PI_F; __sincosf(ph, &sp, &cp);
            fdst[(r+8)*64 + cn] = cp; fdst[(r+8)*64 + 32 + cn] = sp;
            ph = tanhf(c[mt][nt][3] + b1v) * PI_F; __sincosf(ph, &sp, &cp);
            fdst[(r+8)*64 + cn+1] = cp; fdst[(r+8)*64 + 32 + cn+1] = sp;
        }
    }
    // gates only in the k-path blocks
    if (!isq) {
        for (int rr = 0; rr < 16; rr++) {
            int r = row0 + w*16 + rr;
            float p0 = 0.f, p1 = 0.f;
            #pragma unroll
            for (int i = lane; i < 64; i += 32) {
                float gv = g_g1[r*64 + i];
                p0 += gv * Wg2[i*2 + 0];
                p1 += gv * Wg2[i*2 + 1];
            }
            #pragma unroll
            for (int off = 16; off; off >>= 1) {
                p0 += __shfl_xor_sync(~0u, p0, off);
                p1 += __shfl_xor_sync(~0u, p1, off);
            }
            if (lane == 0) {
                float l0 = p0 + bg2[0], l1 = p1 + bg2[1];
                float m = fmaxf(l0, l1);
                float e0 = __expf(l0 - m), e1 = __expf(l1 - m);
                float inv = 1.f / (e0 + e1);
                g_gates[r*2 + 0] = e0 * inv;
                g_gates[r*2 + 1] = e1 * inv;
            }
        }
    }
}

// ======== Kernel 3a+5 merged (+ pos prefix): chunk states || scores || pos-scan =======
// blocks [0,64): k3a; [64,96): k5 scores; [96,100): pos prefix (needs psnap from k23b).
__global__ __launch_bounds__(256) void k3a5_mma()
{
    __shared__ float sraw[10240];
    int tid = threadIdx.x;
    int w = tid >> 5, lane = tid & 31;
    int lq = lane >> 2, lr = lane & 3;

    if (blockIdx.x >= 96) {
        // ---- pos exclusive prefix over 64 s-groups ----
        int e = (blockIdx.x - 96) * 256 + tid;
        if (e < 1024) {
            int b = e >> 9, rd = e & 511;
            float v[64];
            #pragma unroll
            for (int s = 0; s < 64; s++)
                v[s] = g_psnap[((b * 64 + s) * 4 + 3) * 512 + rd];
            float run = 0.f;
            #pragma unroll
            for (int s = 0; s < 64; s++) {
                g_pprefix[(b * 64 + s) * 512 + rd] = run;
                run += v[s];
            }
        }
        return;
    }

    if (blockIdx.x < 64) {
        float (*Kl)[16][68]  = (float(*)[16][68])sraw;
        float (*Bs)[16][132] = (float(*)[16][132])(sraw + 2176);
        int bc = blockIdx.x & 31;
        int b = bc >> 4, c = bc & 15;
        int d0 = (blockIdx.x >> 5) * 128;
        int row0 = b * LL + c * CC;
        int wm = (w & 1) * 32, wn = (w >> 1) * 32;
        int af4 = (tid & 15) * 4, al = tid >> 4;
        int rB = tid >> 5, cB = (tid & 31) * 4;
        float acc[2][4][4] = {};
        float4 av, bv0, bv1;

        av  = *(const float4*)&g_kf[(row0 + al) * 64 + af4];
        bv0 = *(const float4*)&g_vc[(row0 + rB) * 256 + d0 + cB];
        bv1 = *(const float4*)&g_vc[(row0 + rB + 8) * 256 + d0 + cB];
        *(float4*)&Kl[0][al][af4] = av;
        *(float4*)&Bs[0][rB][cB] = bv0;
        *(float4*)&Bs[0][rB+8][cB] = bv1;
        __syncthreads();

        for (int s = 0; s < 8; s++) {
            int cur = s & 1;
            if (s < 7) {
                int kn = (s + 1) * 16;
                av  = *(const float4*)&g_kf[(row0 + kn + al) * 64 + af4];
                bv0 = *(const float4*)&g_vc[(row0 + kn + rB) * 256 + d0 + cB];
                bv1 = *(const float4*)&g_vc[(row0 + kn + rB + 8) * 256 + d0 + cB];
            }
            #pragma unroll
            for (int ks = 0; ks < 2; ks++) {
                unsigned a[2][4];
                #pragma unroll
                for (int mt = 0; mt < 2; mt++) {
                    int rr = wm + mt*16 + lq;
                    int cc = ks*8 + lr;
                    a[mt][0] = __float_as_uint(Kl[cur][cc][rr]);
                    a[mt][1] = __float_as_uint(Kl[cur][cc][rr+8]);
                    a[mt][2] = __float_as_uint(Kl[cur][cc+4][rr]);
                    a[mt][3] = __float_as_uint(Kl[cur][cc+4][rr+8]);
                }
                #pragma unroll
                for (int nt = 0; nt < 4; nt++) {
                    int bn = wn + nt*8 + lq;
                    unsigned b0 = __float_as_uint(Bs[cur][ks*8+lr][bn]);
                    unsigned b1 = __float_as_uint(Bs[cur][ks*8+lr+4][bn]);
                    #pragma unroll
                    for (int mt = 0; mt < 2; mt++)
                        mma_tf32(acc[mt][nt], a[mt][0], a[mt][1], a[mt][2], a[mt][3], b0, b1);
                }
            }
            if (s < 7) {
                int nb = cur ^ 1;
                *(float4*)&Kl[nb][al][af4] = av;
                *(float4*)&Bs[nb][rB][cB] = bv0;
                *(float4*)&Bs[nb][rB+8][cB] = bv1;
            }
            __syncthreads();
        }
        int base = bc * 64 * 256;
        #pragma unroll
        for (int mt = 0; mt < 2; mt++) {
            #pragma unroll
            for (int nt = 0; nt < 4; nt++) {
                int f = wm + mt*16 + lq;
                int dd = d0 + wn + nt*8 + lr*2;
                *(float2*)&g_S[base + f * 256 + dd] = make_float2(acc[mt][nt][0], acc[mt][nt][1]);
                *(float2*)&g_S[base + (f+8) * 256 + dd] = make_float2(acc[mt][nt][2], acc[mt][nt][3]);
            }
        }
        return;
    }

    {
        float (*As)[128][20] = (float(*)[128][20])sraw;
        float (*Ks)[128][20] = (float(*)[128][20])(sraw + 5120);
        int bc = blockIdx.x - 64;
        int b = bc >> 4, c = bc & 15;
        int row0 = b * LL + c * CC;
        int wm = (w & 3) * 32;
        int wn = (w >> 2) * 64;
        int r0 = tid >> 2, c4 = (tid & 3) * 4;
        float acc[2][8][4] = {};
        float4 a0v, a1v, u0, u1;

        a0v = *(const float4*)&g_qf[(row0 + r0) * 64 + c4];
        a1v = *(const float4*)&g_qf[(row0 + r0 + 64) * 64 + c4];
        u0  = *(const float4*)&g_kf[(row0 + r0) * 64 + c4];
        u1  = *(const float4*)&g_kf[(row0 + r0 + 64) * 64 + c4];
        *(float4*)&As[0][r0][c4] = a0v;
        *(float4*)&As[0][r0+64][c4] = a1v;
        *(float4*)&Ks[0][r0][c4] = u0;
        *(float4*)&Ks[0][r0+64][c4] = u1;
        __syncthreads();

        for (int s = 0; s < 4; s++) {
            int cur = s & 1;
            if (s < 3) {
                int kn = (s + 1) * 16;
                a0v = *(const float4*)&g_qf[(row0 + r0) * 64 + kn + c4];
                a1v = *(const float4*)&g_qf[(row0 + r0 + 64) * 64 + kn + c4];
                u0  = *(const float4*)&g_kf[(row0 + r0) * 64 + kn + c4];
                u1  = *(const float4*)&g_kf[(row0 + r0 + 64) * 64 + kn + c4];
            }
            #pragma unroll
            for (int ks = 0; ks < 2; ks++) {
                unsigned a[2][4];
                #pragma unroll
                for (int mt = 0; mt < 2; mt++) {
                    int rr = wm + mt*16 + lq;
                    int cc = ks*8 + lr;
                    a[mt][0] = __float_as_uint(As[cur][rr][cc]);
                    a[mt][1] = __float_as_uint(As[cur][rr+8][cc]);
                    a[mt][2] = __float_as_uint(As[cur][rr][cc+4]);
                    a[mt][3] = __float_as_uint(As[cur][rr+8][cc+4]);
                }
                #pragma unroll
                for (int nt = 0; nt < 8; nt++) {
                    int bn = wn + nt*8 + lq;
                    unsigned b0 = __float_as_uint(Ks[cur][bn][ks*8+lr]);
                    unsigned b1 = __float_as_uint(Ks[cur][bn][ks*8+lr+4]);
                    #pragma unroll
                    for (int mt = 0; mt < 2; mt++)
                        mma_tf32(acc[mt][nt], a[mt][0], a[mt][1], a[mt][2], a[mt][3], b0, b1);
                }
            }
            if (s < 3) {
                int nb = cur ^ 1;
                *(float4*)&As[nb][r0][c4] = a0v;
                *(float4*)&As[nb][r0+64][c4] = a1v;
                *(float4*)&Ks[nb][r0][c4] = u0;
                *(float4*)&Ks[nb][r0+64][c4] = u1;
            }
            __syncthreads();
        }
        int sb = bc * CC * CC;
        #pragma unroll
        for (int mt = 0; mt < 2; mt++) {
            #pragma unroll
            for (int nt = 0; nt < 8; nt++) {
                int la = wm + mt*16 + lq;
                int lb = la + 8;
                int j0 = wn + nt*8 + lr*2;
                int j1 = j0 + 1;
                *(float2*)&g_scores[sb + la*128 + j0] =
                    make_float2(j0 <= la ? acc[mt][nt][0] : 0.f, j1 <= la ? acc[mt][nt][1] : 0.f);
                *(float2*)&g_scores[sb + lb*128 + j0] =
                    make_float2(j0 <= lb ? acc[mt][nt][2] : 0.f, j1 <= lb ? acc[mt][nt][3] : 0.f);
            }
        }
    }
}

// ================= Kernel 4: content exclusive prefix only =================
__global__ __launch_bounds__(256) void k4_prefix()
{
    int tid = threadIdx.x;
    int idx = blockIdx.x * 256 + tid;
    int b = idx >> 14, rd = idx & 16383;
    float v[16];
    #pragma unroll
    for (int c = 0; c < 16; c++)
        v[c] = g_S[(b * 16 + c) * 16384 + rd];
    float run = 0.f;
    #pragma unroll
    for (int c = 0; c < 16; c++) {
        g_P[(b * 16 + c) * 16384 + rd] = run;
        run += v[c];
    }
}

// ================= Kernel 6: content output, 128-wide d tiles (3-stage) ===============
// grid (32, 2): d0 = blockIdx.y * 128
__global__ __launch_bounds__(256) void k6_mma()
{
    extern __shared__ __align__(16) float smem6[];
    float (*As)[128][20] = (float(*)[128][20])smem6;            // 3*2560
    float (*Bs)[16][132] = (float(*)[16][132])(smem6 + 7680);   // 3*2112
    int bc = blockIdx.x; int b = bc >> 4, c = bc & 15;
    int d0 = blockIdx.y * 128;
    int row0 = b * LL + c * CC;
    int tid = threadIdx.x;
    int w = tid >> 5, lane = tid & 31;
    int wm = (w & 3) * 32;
    int wn = (w >> 2) * 64;
    int lq = lane >> 2, lr = lane & 3;
    int r0 = tid >> 2, c4 = (tid & 3) * 4;
    int rB = tid >> 5, cB = (tid & 31) * 4;
    int Pbase = bc * 64 * 256;
    int sbase = bc * CC * CC;
    float acc[2][8][4] = {};

    #pragma unroll
    for (int p = 0; p < 2; p++) {
        int k0 = p * 16;
        int kga = k0 + c4;
        const float *sa0, *sa1;
        if (kga < 64) {
            sa0 = &g_qf[(row0 + r0) * 64 + kga];
            sa1 = &g_qf[(row0 + r0 + 64) * 64 + kga];
        } else {
            sa0 = &g_scores[sbase + r0 * 128 + kga - 64];
            sa1 = &g_scores[sbase + (r0 + 64) * 128 + kga - 64];
        }
        int kb0 = k0 + rB, kb1 = k0 + rB + 8;
        const float* sb0 = (kb0 < 64) ? &g_P[Pbase + kb0 * 256 + d0 + cB]
                                      : &g_vc[(row0 + kb0 - 64) * 256 + d0 + cB];
        const float* sb1 = (kb1 < 64) ? &g_P[Pbase + kb1 * 256 + d0 + cB]
                                      : &g_vc[(row0 + kb1 - 64) * 256 + d0 + cB];
        cp_async16(&As[p][r0][c4], sa0);
        cp_async16(&As[p][r0+64][c4], sa1);
        cp_async16(&Bs[p][rB][cB], sb0);
        cp_async16(&Bs[p][rB+8][cB], sb1);
        cp_commit();
    }

    for (int s = 0; s < 12; s++) {
        if (s < 11) cp_wait1(); else cp_wait0();
        __syncthreads();
        int cur = s % 3;
        #pragma unroll
        for (int ks = 0; ks < 2; ks++) {
            unsigned a[2][4];
            #pragma unroll
            for (int mt = 0; mt < 2; mt++) {
                int rr = wm + mt*16 + lq;
                int cc = ks*8 + lr;
                a[mt][0] = __float_as_uint(As[cur][rr][cc]);
                a[mt][1] = __float_as_uint(As[cur][rr+8][cc]);
                a[mt][2] = __float_as_uint(As[cur][rr][cc+4]);
                a[mt][3] = __float_as_uint(As[cur][rr+8][cc+4]);
            }
            #pragma unroll
            for (int nt = 0; nt < 8; nt++) {
                int bn = wn + nt*8 + lq;
                unsigned b0 = __float_as_uint(Bs[cur][ks*8+lr][bn]);
                unsigned b1 = __float_as_uint(Bs[cur][ks*8+lr+4][bn]);
                #pragma unroll
                for (int mt = 0; mt < 2; mt++)
                    mma_tf32(acc[mt][nt], a[mt][0], a[mt][1], a[mt][2], a[mt][3], b0, b1);
            }
        }
        if (s < 10) {
            int st = (s + 2) % 3;
            int k0 = (s + 2) * 16;
            int kga = k0 + c4;
            const float *sa0, *sa1;
            if (kga < 64) {
                sa0 = &g_qf[(row0 + r0) * 64 + kga];
                sa1 = &g_qf[(row0 + r0 + 64) * 64 + kga];
            } else {
                sa0 = &g_scores[sbase + r0 * 128 + kga - 64];
                sa1 = &g_scores[sbase + (r0 + 64) * 128 + kga - 64];
            }
            int kb0 = k0 + rB, kb1 = k0 + rB + 8;
            const float* sb0 = (kb0 < 64) ? &g_P[Pbase + kb0 * 256 + d0 + cB]
                                          : &g_vc[(row0 + kb0 - 64) * 256 + d0 + cB];
            const float* sb1 = (kb1 < 64) ? &g_P[Pbase + kb1 * 256 + d0 + cB]
                                          : &g_vc[(row0 + kb1 - 64) * 256 + d0 + cB];
            cp_async16(&As[st][r0][c4], sa0);
            cp_async16(&As[st][r0+64][c4], sa1);
            cp_async16(&Bs[st][rB][cB], sb0);
            cp_async16(&Bs[st][rB+8][cB], sb1);
            cp_commit();
        }
    }
    #pragma unroll
    for (int mt = 0; mt < 2; mt++) {
        #pragma unroll
        for (int nt = 0; nt < 8; nt++) {
            int la = wm + mt*16 + lq;
            int lb = la + 8;
            int cc = d0 + wn + nt*8 + lr*2;
            float sa = rsqrtf((float)((c*CC + la + 1) * KK));
            float sb2 = rsqrtf((float)((c*CC + lb + 1) * KK));
            *(float2*)&g_cont[(row0 + la) * 256 + cc] =
                make_float2(acc[mt][nt][0] * sa, acc[mt][nt][1] * sa);
            *(float2*)&g_cont[(row0 + lb) * 256 + cc] =
                make_float2(acc[mt][nt][2] * sb2, acc[mt][nt][3] * sb2);
        }
    }
}

// ======== Kernel 7: pos scan (cached sincos) + gate combine + LayerNorm =========
__global__ __launch_bounds__(256) void k7_poscomb(
    const float* __restrict__ ln_g, const float* __restrict__ ln_b)
{
    __shared__ float comb[8][257];
    int blk = blockIdx.x;
    int j = blk & 3;
    int s = (blk >> 2) & 63;
    int b = blk >> 8;
    int row0 = b * LL + s * 32 + j * 8;
    int l0 = s * 32 + j * 8;
    int d = threadIdx.x;
    float ar = g_pprefix[(b * 64 + s) * 512 + d];
    float ai = g_pprefix[(b * 64 + s) * 512 + 256 + d];
    if (j > 0) {
        int snapbase = ((b * 64 + s) * 4 + j - 1) * 512;
        ar += g_psnap[snapbase + d];
        ai += g_psnap[snapbase + 256 + d];
    }
    float vp[8], cph[8], sph[8], cv[8];
    #pragma unroll
    for (int lt = 0; lt < 8; lt++) {
        vp[lt]  = g_vp[(row0 + lt) * 256 + d];
        cph[lt] = g_cph[(l0 + lt) * 256 + d];
        sph[lt] = g_sph[(l0 + lt) * 256 + d];
        cv[lt]  = g_cont[(row0 + lt) * 256 + d];
    }
    #pragma unroll
    for (int lt = 0; lt < 8; lt++) {
        ar += vp[lt] * cph[lt]; ai += vp[lt] * sph[lt];
        float pret = (ar * cph[lt] + ai * sph[lt]) * rsqrtf((float)(l0 + lt + 1));
        float g0 = g_gates[(row0 + lt) * 2], g1v = g_gates[(row0 + lt) * 2 + 1];
        comb[lt][d] = g0 * pret + g1v * cv[lt];
    }
    __syncthreads();
    int w = d >> 5, lane = d & 31;
    int r = row0 + w;
    float vals[8]; float s1 = 0.f, s2 = 0.f;
    #pragma unroll
    for (int k = 0; k < 8; k++) {
        float v = comb[w][lane + 32*k];
        vals[k] = v; s1 += v; s2 += v*v;
    }
    #pragma unroll
    for (int off = 16; off; off >>= 1) {
        s1 += __shfl_xor_sync(~0u, s1, off);
        s2 += __shfl_xor_sync(~0u, s2, off);
    }
    float mu = s1 * (1.f/256.f);
    float var = s2 * (1.f/256.f) - mu*mu;
    float rstd = rsqrtf(var + 1e-5f);
    #pragma unroll
    for (int k = 0; k < 8; k++) {
        int dd = lane + 32*k;
        g_norm[r*256 + dd] = (vals[k] - mu) * rstd * ln_g[dd] + ln_b[dd];
    }
}

// ====== Kernel 8: out = x + normed @ Wo + bo, 128x128 tiles (3-stage cp.async) ========
// grid (32, 2)
__global__ __launch_bounds__(256) void k8_mma(
    const float* __restrict__ x, const float* __restrict__ Wo,
    const float* __restrict__ bo, float* __restrict__ out)
{
    extern __shared__ __align__(16) float smem8[];
    float (*As)[128][20] = (float(*)[128][20])smem8;
    float (*Bs)[16][132] = (float(*)[16][132])(smem8 + 7680);
    int row0 = blockIdx.x * 128;
    int colbase = blockIdx.y * 128;
    int tid = threadIdx.x;
    int w = tid >> 5, lane = tid & 31;
    int wm = (w & 3) * 32;
    int wn = (w >> 2) * 64;
    int lq = lane >> 2, lr = lane & 3;
    int r0 = tid >> 2, c4 = (tid & 3) * 4;
    int rB = tid >> 5, cB = (tid & 31) * 4;
    float c[2][8][4] = {};

    #pragma unroll
    for (int p = 0; p < 2; p++) {
        int k0 = p * 16;
        cp_async16(&As[p][r0][c4],    &g_norm[(row0 + r0) * 256 + k0 + c4]);
        cp_async16(&As[p][r0+64][c4], &g_norm[(row0 + r0 + 64) * 256 + k0 + c4]);
        cp_async16(&Bs[p][rB][cB],   &Wo[(k0 + rB) * 256 + colbase + cB]);
        cp_async16(&Bs[p][rB+8][cB], &Wo[(k0 + rB + 8) * 256 + colbase + cB]);
        cp_commit();
    }

    for (int s = 0; s < 16; s++) {
        if (s < 15) cp_wait1(); else cp_wait0();
        __syncthreads();
        int cur = s % 3;
        #pragma unroll
        for (int ks = 0; ks < 2; ks++) {
            unsigned a[2][4];
            #pragma unroll
            for (int mt = 0; mt < 2; mt++) {
                int rr = wm + mt*16 + lq;
                int cc = ks*8 + lr;
                a[mt][0] = __float_as_uint(As[cur][rr][cc]);
                a[mt][1] = __float_as_uint(As[cur][rr+8][cc]);
                a[mt][2] = __float_as_uint(As[cur][rr][cc+4]);
                a[mt][3] = __float_as_uint(As[cur][rr+8][cc+4]);
            }
            #pragma unroll
            for (int nt = 0; nt < 8; nt++) {
                int bn = wn + nt*8 + lq;
                unsigned b0 = __float_as_uint(Bs[cur][ks*8+lr][bn]);
                unsigned b1 = __float_as_uint(Bs[cur][ks*8+lr+4][bn]);
                #pragma unroll
                for (int mt = 0; mt < 2; mt++)
                    mma_tf32(c[mt][nt], a[mt][0], a[mt][1], a[mt][2], a[mt][3], b0, b1);
            }
        }
        if (s < 14) {
            int st = (s + 2) % 3;
            int k0 = (s + 2) * 16;
            cp_async16(&As[st][r0][c4],    &g_norm[(row0 + r0) * 256 + k0 + c4]);
            cp_async16(&As[st][r0+64][c4], &g_norm[(row0 + r0 + 64) * 256 + k0 + c4]);
            cp_async16(&Bs[st][rB][cB],   &Wo[(k0 + rB) * 256 + colbase + cB]);
            cp_async16(&Bs[st][rB+8][cB], &Wo[(k0 + rB + 8) * 256 + colbase + cB]);
            cp_commit();
        }
    }
    #pragma unroll
    for (int mt = 0; mt < 2; mt++) {
        #pragma unroll
        for (int nt = 0; nt < 8; nt++) {
            int r = row0 + wm + mt*16 + lq;
            int cc = colbase + wn + nt*8 + lr*2;
            float b0v = bo[cc], b1v = bo[cc+1];
            float2 x0 = *(const float2*)&x[r * 256 + cc];
            float2 x1 = *(const float2*)&x[(r+8) * 256 + cc];
            *(float2*)&out[r * 256 + cc] =
                make_float2(c[mt][nt][0] + b0v + x0.x, c[mt][nt][1] + b1v + x0.y);
            *(float2*)&out[(r+8) * 256 + cc] =
                make_float2(c[mt][nt][2] + b0v + x1.x, c[mt][nt][3] + b1v + x1.y);
        }
    }
}

// ================= launcher =================
extern "C" void kernel_launch(void* const* d_in, const int* in_sizes, int n_in,
                              void* d_out, int out_size)
{
    const float* x   = (const float*)d_in[0];
    const float* bp  = (const float*)d_in[1];
    const float* Wk1 = (const float*)d_in[2];
    const float* bk1 = (const float*)d_in[3];
    const float* Wk2 = (const float*)d_in[4];
    const float* bk2 = (const float*)d_in[5];
    const float* Wq1 = (const float*)d_in[6];
    const float* bq1 = (const float*)d_in[7];
    const float* Wq2 = (const float*)d_in[8];
    const float* bq2 = (const float*)d_in[9];
    const float* Wvc = (const float*)d_in[10];
    const float* bvc = (const float*)d_in[11];
    const float* Wvp = (const float*)d_in[12];
    const float* bvp = (const float*)d_in[13];
    const float* Wg1 = (const float*)d_in[14];
    const float* bg1 = (const float*)d_in[15];
    const float* Wg2 = (const float*)d_in[16];
    const float* bg2 = (const float*)d_in[17];
    const float* lng = (const float*)d_in[18];
    const float* lnb = (const float*)d_in[19];
    const float* Wo  = (const float*)d_in[20];
    const float* bo  = (const float*)d_in[21];
    float* out = (float*)d_out;

    cudaFuncSetAttribute(k1_mma, cudaFuncAttributeMaxDynamicSharedMemorySize, 57344);
    cudaFuncSetAttribute(k6_mma, cudaFuncAttributeMaxDynamicSharedMemorySize, 57344);
    cudaFuncSetAttribute(k8_mma, cudaFuncAttributeMaxDynamicSharedMemorySize, 57344);
    k1_mma<<<dim3(32, 9), 256, 56064>>>(x, Wk1, bk1, Wq1, bq1, Wvc, bvc, Wvp, bvp, Wg1, bg1);
    k23b_mma<<<128, 256>>>(Wk2, bk2, Wq2, bq2, Wg2, bg2, bp);
    k3a5_mma<<<100, 256>>>();
    k4_prefix<<<128, 256>>>();
    k6_mma<<<dim3(32, 2), 256, 56064>>>();
    k7_poscomb<<<512, 256>>>(lng, lnb);
    k8_mma<<<dim3(32, 2), 256, 56064>>>(x, Wo, bo, out);
}

// round 16
// speedup vs baseline: 1.1057x; 1.1057x over previous
#include <cuda_runtime.h>
#include <cuda_bf16.h>
#include <math.h>

// Problem constants
#define Bb 2
#define LL 2048
#define DD 256
#define KK 32
#define FF 64          // 2*K feature dim
#define MM (Bb*LL)     // 4096 rows
#define CC 128         // chunk size
#define NC (LL/CC)     // 16 chunks per batch
#define PI_F 3.14159265358979323846f

// ---------------- scratch (device globals; no allocation allowed) ----------------
__device__ float g_hk[MM*DD];
__device__ float g_hq[MM*DD];
__device__ float g_vc[MM*DD];
__device__ float g_vp[MM*DD];
__device__ float g_g1[MM*64];
__device__ float g_kf[MM*FF];
__device__ float g_qf[MM*FF];
__device__ float g_gates[MM*2];
__device__ float g_S[Bb*NC*FF*DD];         // per-chunk content state sums (mma)
__device__ float g_P[Bb*NC*FF*DD];         // chunk-level exclusive prefix of states
__device__ float g_psnap[Bb*64*4*2*DD];    // pos accum snapshots every 8 rows (inclusive)
__device__ float g_pprefix[Bb*64*2*DD];    // exclusive prefix at 32-row granularity
__device__ float g_scores[Bb*NC*CC*CC];    // intra-chunk masked scores
__device__ float g_cont[MM*DD];
__device__ float g_norm[MM*DD];
__device__ float g_cph[LL*DD];             // cached cos(base_phases[:LL])
__device__ float g_sph[LL*DD];             // cached sin(base_phases[:LL])

// mma consumes raw f32 bit patterns as tf32 (HW truncates mantissa; no cvt needed)
__device__ __forceinline__ void mma_tf32(float c[4],
    unsigned a0, unsigned a1, unsigned a2, unsigned a3,
    unsigned b0, unsigned b1)
{
    asm volatile(
        "mma.sync.aligned.m16n8k8.row.col.f32.tf32.tf32.f32 "
        "{%0,%1,%2,%3}, {%4,%5,%6,%7}, {%8,%9}, {%0,%1,%2,%3};"
        : "+f"(c[0]), "+f"(c[1]), "+f"(c[2]), "+f"(c[3])
        : "r"(a0), "r"(a1), "r"(a2), "r"(a3), "r"(b0), "r"(b1));
}

// ---------------- cp.async helpers ----------------
__device__ __forceinline__ void cp_async16(void* smem_dst, const void* gsrc) {
    unsigned saddr = (unsigned)__cvta_generic_to_shared(smem_dst);
    asm volatile("cp.async.cg.shared.global [%0], [%1], 16;" :: "r"(saddr), "l"(gsrc));
}
__device__ __forceinline__ void cp_commit() {
    asm volatile("cp.async.commit_group;");
}
__device__ __forceinline__ void cp_wait1() {
    asm volatile("cp.async.wait_group 1;");
}
__device__ __forceinline__ void cp_wait0() {
    asm volatile("cp.async.wait_group 0;");
}

// ================= Kernel 1: fused first-layer GEMMs, 128x128 tiles (3-stage) =========
// grid (32, 9): ct<8 -> [hk|hq|vc|vp] x 2 col-halves; ct==8 -> g1 (64 cols, predicated)
__global__ __launch_bounds__(256) void k1_mma(
    const float* __restrict__ x,
    const float* __restrict__ Wk1, const float* __restrict__ bk1,
    const float* __restrict__ Wq1, const float* __restrict__ bq1,
    const float* __restrict__ Wvc, const float* __restrict__ bvc,
    const float* __restrict__ Wvp, const float* __restrict__ bvp,
    const float* __restrict__ Wg1, const float* __restrict__ bg1)
{
    extern __shared__ __align__(16) float smem[];
    float (*As)[128][20] = (float(*)[128][20])smem;            // 3*2560 floats
    float (*Bs)[16][132] = (float(*)[16][132])(smem + 7680);   // 3*2112 floats
    int ct = blockIdx.y;
    const float* W; const float* bias; float* outp; int Nseg; int act; int colbase;
    if (ct < 8) {
        int seg = ct >> 1;
        colbase = (ct & 1) * 128;
        Nseg = 256;
        if (seg == 0)      { W = Wk1; bias = bk1; outp = g_hk; act = 1; }
        else if (seg == 1) { W = Wq1; bias = bq1; outp = g_hq; act = 1; }
        else if (seg == 2) { W = Wvc; bias = bvc; outp = g_vc; act = 0; }
        else               { W = Wvp; bias = bvp; outp = g_vp; act = 0; }
    } else {
        W = Wg1; bias = bg1; outp = g_g1; Nseg = 64; act = 2; colbase = 0;
    }
    int row0 = blockIdx.x * 128;
    int tid = threadIdx.x;
    int w = tid >> 5, lane = tid & 31;
    int wm = (w & 3) * 32;
    int wn = (w >> 2) * 64;
    int lq = lane >> 2, lr = lane & 3;
    int r0 = tid >> 2, c4 = (tid & 3) * 4;
    int rB = tid >> 5, cB = (tid & 31) * 4;
    bool bok = (colbase + cB) < Nseg;
    float c[2][8][4] = {};

    #pragma unroll
    for (int p = 0; p < 2; p++) {
        int k0 = p * 16;
        cp_async16(&As[p][r0][c4],    &x[(row0 + r0) * 256 + k0 + c4]);
        cp_async16(&As[p][r0+64][c4], &x[(row0 + r0 + 64) * 256 + k0 + c4]);
        if (bok) {
            cp_async16(&Bs[p][rB][cB],   &W[(k0 + rB) * Nseg + colbase + cB]);
            cp_async16(&Bs[p][rB+8][cB], &W[(k0 + rB + 8) * Nseg + colbase + cB]);
        }
        cp_commit();
    }

    for (int s = 0; s < 16; s++) {
        if (s < 15) cp_wait1(); else cp_wait0();
        __syncthreads();
        int cur = s % 3;
        #pragma unroll
        for (int ks = 0; ks < 2; ks++) {
            unsigned a[2][4];
            #pragma unroll
            for (int mt = 0; mt < 2; mt++) {
                int rr = wm + mt*16 + lq;
                int cc = ks*8 + lr;
                a[mt][0] = __float_as_uint(As[cur][rr][cc]);
                a[mt][1] = __float_as_uint(As[cur][rr+8][cc]);
                a[mt][2] = __float_as_uint(As[cur][rr][cc+4]);
                a[mt][3] = __float_as_uint(As[cur][rr+8][cc+4]);
            }
            #pragma unroll
            for (int nt = 0; nt < 8; nt++) {
                int bn = wn + nt*8 + lq;
                unsigned b0 = __float_as_uint(Bs[cur][ks*8+lr][bn]);
                unsigned b1 = __float_as_uint(Bs[cur][ks*8+lr+4][bn]);
                #pragma unroll
                for (int mt = 0; mt < 2; mt++)
                    mma_tf32(c[mt][nt], a[mt][0], a[mt][1], a[mt][2], a[mt][3], b0, b1);
            }
        }
        if (s < 14) {
            int st = (s + 2) % 3;
            int k0 = (s + 2) * 16;
            cp_async16(&As[st][r0][c4],    &x[(row0 + r0) * 256 + k0 + c4]);
            cp_async16(&As[st][r0+64][c4], &x[(row0 + r0 + 64) * 256 + k0 + c4]);
            if (bok) {
                cp_async16(&Bs[st][rB][cB],   &W[(k0 + rB) * Nseg + colbase + cB]);
                cp_async16(&Bs[st][rB+8][cB], &W[(k0 + rB + 8) * Nseg + colbase + cB]);
            }
            cp_commit();
        }
    }
    #pragma unroll
    for (int mt = 0; mt < 2; mt++) {
        #pragma unroll
        for (int nt = 0; nt < 8; nt++) {
            int cc = colbase + wn + nt*8 + lr*2;
            if (cc < Nseg) {
                int r = row0 + wm + mt*16 + lq;
                float b0v = bias[cc], b1v = bias[cc+1];
                float v00 = c[mt][nt][0] + b0v, v01 = c[mt][nt][1] + b1v;
                float v10 = c[mt][nt][2] + b0v, v11 = c[mt][nt][3] + b1v;
                if (act == 1) { v00 = tanhf(v00); v01 = tanhf(v01); v10 = tanhf(v10); v11 = tanhf(v11); }
                else if (act == 2) { v00 = fmaxf(v00,0.f); v01 = fmaxf(v01,0.f); v10 = fmaxf(v10,0.f); v11 = fmaxf(v11,0.f); }
                *(float2*)&outp[r * Nseg + cc] = make_float2(v00, v01);
                *(float2*)&outp[(r+8) * Nseg + cc] = make_float2(v10, v11);
            }
        }
    }
}

// ===== Kernel 2+3b merged: split phase GEMMs (3-stage cp.async) || pos partials =======
// blocks [0,32): k-path GEMM + gates; [32,64): q-path GEMM;
// blocks [64,128): pos partials for BOTH batches (one sincos, cached to g_cph/g_sph).
__global__ __launch_bounds__(256) void k23b_mma(
    const float* __restrict__ Wk2, const float* __restrict__ bk2,
    const float* __restrict__ Wq2, const float* __restrict__ bq2,
    const float* __restrict__ Wg2, const float* __restrict__ bg2,
    const float* __restrict__ base_phases)
{
    __shared__ __align__(16) float As[3][128][20];
    __shared__ __align__(16) float Bs[3][16][36];
    int tid = threadIdx.x;
    int bx = blockIdx.x;

    if (bx >= 64) {
        // ---- pos partial sums for both batches + sincos cache ----
        int s = bx - 64;            // 0..63
        int l0 = s * 32;
        int row0_0 = l0;            // b = 0
        int row0_1 = LL + l0;       // b = 1
        int d = tid;
        float par0 = 0.f, pai0 = 0.f, par1 = 0.f, pai1 = 0.f;
        #pragma unroll
        for (int g = 0; g < 4; g++) {
            float ph8[8], v0[8], v1[8];
            #pragma unroll
            for (int j = 0; j < 8; j++) {
                ph8[j] = base_phases[(l0 + g*8 + j) * 256 + d];
                v0[j] = g_vp[(row0_0 + g*8 + j) * 256 + d];
                v1[j] = g_vp[(row0_1 + g*8 + j) * 256 + d];
            }
            #pragma unroll
            for (int j = 0; j < 8; j++) {
                float sp, cp; __sincosf(ph8[j], &sp, &cp);
                int l = l0 + g*8 + j;
                g_cph[l*256 + d] = cp;
                g_sph[l*256 + d] = sp;
                par0 += v0[j] * cp; pai0 += v0[j] * sp;
                par1 += v1[j] * cp; pai1 += v1[j] * sp;
            }
            int sb0 = (s * 4 + g) * 512;
            int sb1 = ((64 + s) * 4 + g) * 512;
            g_psnap[sb0 + d] = par0; g_psnap[sb0 + 256 + d] = pai0;
            g_psnap[sb1 + d] = par1; g_psnap[sb1 + 256 + d] = pai1;
        }
        return;
    }

    // ---- phase-feature GEMM: one path per block ----
    bool isq = (bx >= 32);
    int row0 = (bx & 31) * 128;
    const float* H  = isq ? g_hq : g_hk;
    const float* W2 = isq ? Wq2 : Wk2;
    const float* bvec = isq ? bq2 : bk2;
    float* fdst = isq ? g_qf : g_kf;

    int w = tid >> 5, lane = tid & 31;
    int wm = (w & 3) * 32;
    int wn = (w >> 2) * 16;
    int lq = lane >> 2, lr = lane & 3;
    int r0 = tid >> 2, c4 = (tid & 3) * 4;
    int brB = tid >> 3, bc4B = (tid & 7) * 4;   // valid for tid < 128
    float c[2][2][4] = {};

    #pragma unroll
    for (int p = 0; p < 2; p++) {
        int k0 = p * 16;
        cp_async16(&As[p][r0][c4],    &H[(row0 + r0) * 256 + k0 + c4]);
        cp_async16(&As[p][r0+64][c4], &H[(row0 + r0 + 64) * 256 + k0 + c4]);
        if (tid < 128)
            cp_async16(&Bs[p][brB][bc4B], &W2[(k0 + brB) * 32 + bc4B]);
        cp_commit();
    }

    for (int s = 0; s < 16; s++) {
        if (s < 15) cp_wait1(); else cp_wait0();
        __syncthreads();
        int cur = s % 3;
        #pragma unroll
        for (int ks = 0; ks < 2; ks++) {
            unsigned a[2][4];
            #pragma unroll
            for (int mt = 0; mt < 2; mt++) {
                int rr = wm + mt*16 + lq;
                int cc = ks*8 + lr;
                a[mt][0] = __float_as_uint(As[cur][rr][cc]);
                a[mt][1] = __float_as_uint(As[cur][rr+8][cc]);
                a[mt][2] = __float_as_uint(As[cur][rr][cc+4]);
                a[mt][3] = __float_as_uint(As[cur][rr+8][cc+4]);
            }
            #pragma unroll
            for (int nt = 0; nt < 2; nt++) {
                int bn = wn + nt*8 + lq;
                unsigned b0 = __float_as_uint(Bs[cur][ks*8+lr][bn]);
                unsigned b1 = __float_as_uint(Bs[cur][ks*8+lr+4][bn]);
                #pragma unroll
                for (int mt = 0; mt < 2; mt++)
                    mma_tf32(c[mt][nt], a[mt][0], a[mt][1], a[mt][2], a[mt][3], b0, b1);
            }
        }
        if (s < 14) {
            int st = (s + 2) % 3;
            int k0 = (s + 2) * 16;
            cp_async16(&As[st][r0][c4],    &H[(row0 + r0) * 256 + k0 + c4]);
            cp_async16(&As[st][r0+64][c4], &H[(row0 + r0 + 64) * 256 + k0 + c4]);
            if (tid < 128)
                cp_async16(&Bs[st][brB][bc4B], &W2[(k0 + brB) * 32 + bc4B]);
            cp_commit();
        }
    }

    #pragma unroll
    for (int mt = 0; mt < 2; mt++) {
        #pragma unroll
        for (int nt = 0; nt < 2; nt++) {
            int r = row0 + wm + mt*16 + lq;
            int cn = wn + nt*8 + lr*2;
            float b0v = bvec[cn], b1v = bvec[cn+1];
            float ph;
            float sp, cp;
            ph = tanhf(c[mt][nt][0] + b0v) * PI_F; __sincosf(ph, &sp, &cp);
            fdst[r*64 + cn] = cp; fdst[r*64 + 32 + cn] = sp;
            ph = tanhf(c[mt][nt][1] + b1v) * PI_F; __sincosf(ph, &sp, &cp);
            fdst[r*64 + cn+1] = cp; fdst[r*64 + 32 + cn+1] = sp;
            ph = tanhf(c[mt][nt][2] + b0v) * PI_F; __sincosf(ph, &sp, &cp);
            fdst[(r+8)*64 + cn] = cp; fdst[(r+8)*64 + 32 + cn] = sp;
            ph = tanhf(c[mt][nt][3] + b1v) * PI_F; __sincosf(ph, &sp, &cp);
            fdst[(r+8)*64 + cn+1] = cp; fdst[(r+8)*64 + 32 + cn+1] = sp;
        }
    }
    // gates only in the k-path blocks
    if (!isq) {
        for (int rr = 0; rr < 16; rr++) {
            int r = row0 + w*16 + rr;
            float p0 = 0.f, p1 = 0.f;
            #pragma unroll
            for (int i = lane; i < 64; i += 32) {
                float gv = g_g1[r*64 + i];
                p0 += gv * Wg2[i*2 + 0];
                p1 += gv * Wg2[i*2 + 1];
            }
            #pragma unroll
            for (int off = 16; off; off >>= 1) {
                p0 += __shfl_xor_sync(~0u, p0, off);
                p1 += __shfl_xor_sync(~0u, p1, off);
            }
            if (lane == 0) {
                float l0 = p0 + bg2[0], l1 = p1 + bg2[1];
                float m = fmaxf(l0, l1);
                float e0 = __expf(l0 - m), e1 = __expf(l1 - m);
                float inv = 1.f / (e0 + e1);
                g_gates[r*2 + 0] = e0 * inv;
                g_gates[r*2 + 1] = e1 * inv;
            }
        }
    }
}

// ======== Kernel 3a+5 merged (+ pos prefix): chunk states || scores || pos-scan =======
// blocks [0,64): k3a; [64,96): k5 scores; [96,100): pos prefix (needs psnap from k23b).
__global__ __launch_bounds__(256) void k3a5_mma()
{
    __shared__ float sraw[10240];
    int tid = threadIdx.x;
    int w = tid >> 5, lane = tid & 31;
    int lq = lane >> 2, lr = lane & 3;

    if (blockIdx.x >= 96) {
        // ---- pos exclusive prefix over 64 s-groups ----
        int e = (blockIdx.x - 96) * 256 + tid;
        if (e < 1024) {
            int b = e >> 9, rd = e & 511;
            float v[64];
            #pragma unroll
            for (int s = 0; s < 64; s++)
                v[s] = g_psnap[((b * 64 + s) * 4 + 3) * 512 + rd];
            float run = 0.f;
            #pragma unroll
            for (int s = 0; s < 64; s++) {
                g_pprefix[(b * 64 + s) * 512 + rd] = run;
                run += v[s];
            }
        }
        return;
    }

    if (blockIdx.x < 64) {
        float (*Kl)[16][68]  = (float(*)[16][68])sraw;
        float (*Bs)[16][132] = (float(*)[16][132])(sraw + 2176);
        int bc = blockIdx.x & 31;
        int b = bc >> 4, c = bc & 15;
        int d0 = (blockIdx.x >> 5) * 128;
        int row0 = b * LL + c * CC;
        int wm = (w & 1) * 32, wn = (w >> 1) * 32;
        int af4 = (tid & 15) * 4, al = tid >> 4;
        int rB = tid >> 5, cB = (tid & 31) * 4;
        float acc[2][4][4] = {};
        float4 av, bv0, bv1;

        av  = *(const float4*)&g_kf[(row0 + al) * 64 + af4];
        bv0 = *(const float4*)&g_vc[(row0 + rB) * 256 + d0 + cB];
        bv1 = *(const float4*)&g_vc[(row0 + rB + 8) * 256 + d0 + cB];
        *(float4*)&Kl[0][al][af4] = av;
        *(float4*)&Bs[0][rB][cB] = bv0;
        *(float4*)&Bs[0][rB+8][cB] = bv1;
        __syncthreads();

        for (int s = 0; s < 8; s++) {
            int cur = s & 1;
            if (s < 7) {
                int kn = (s + 1) * 16;
                av  = *(const float4*)&g_kf[(row0 + kn + al) * 64 + af4];
                bv0 = *(const float4*)&g_vc[(row0 + kn + rB) * 256 + d0 + cB];
                bv1 = *(const float4*)&g_vc[(row0 + kn + rB + 8) * 256 + d0 + cB];
            }
            #pragma unroll
            for (int ks = 0; ks < 2; ks++) {
                unsigned a[2][4];
                #pragma unroll
                for (int mt = 0; mt < 2; mt++) {
                    int rr = wm + mt*16 + lq;
                    int cc = ks*8 + lr;
                    a[mt][0] = __float_as_uint(Kl[cur][cc][rr]);
                    a[mt][1] = __float_as_uint(Kl[cur][cc][rr+8]);
                    a[mt][2] = __float_as_uint(Kl[cur][cc+4][rr]);
                    a[mt][3] = __float_as_uint(Kl[cur][cc+4][rr+8]);
                }
                #pragma unroll
                for (int nt = 0; nt < 4; nt++) {
                    int bn = wn + nt*8 + lq;
                    unsigned b0 = __float_as_uint(Bs[cur][ks*8+lr][bn]);
                    unsigned b1 = __float_as_uint(Bs[cur][ks*8+lr+4][bn]);
                    #pragma unroll
                    for (int mt = 0; mt < 2; mt++)
                        mma_tf32(acc[mt][nt], a[mt][0], a[mt][1], a[mt][2], a[mt][3], b0, b1);
                }
            }
            if (s < 7) {
                int nb = cur ^ 1;
                *(float4*)&Kl[nb][al][af4] = av;
                *(float4*)&Bs[nb][rB][cB] = bv0;
                *(float4*)&Bs[nb][rB+8][cB] = bv1;
            }
            __syncthreads();
        }
        int base = bc * 64 * 256;
        #pragma unroll
        for (int mt = 0; mt < 2; mt++) {
            #pragma unroll
            for (int nt = 0; nt < 4; nt++) {
                int f = wm + mt*16 + lq;
                int dd = d0 + wn + nt*8 + lr*2;
                *(float2*)&g_S[base + f * 256 + dd] = make_float2(acc[mt][nt][0], acc[mt][nt][1]);
                *(float2*)&g_S[base + (f+8) * 256 + dd] = make_float2(acc[mt][nt][2], acc[mt][nt][3]);
            }
        }
        return;
    }

    {
        float (*As)[128][20] = (float(*)[128][20])sraw;
        float (*Ks)[128][20] = (float(*)[128][20])(sraw + 5120);
        int bc = blockIdx.x - 64;
        int b = bc >> 4, c = bc & 15;
        int row0 = b * LL + c * CC;
        int wm = (w & 3) * 32;
        int wn = (w >> 2) * 64;
        int r0 = tid >> 2, c4 = (tid & 3) * 4;
        float acc[2][8][4] = {};
        float4 a0v, a1v, u0, u1;

        a0v = *(const float4*)&g_qf[(row0 + r0) * 64 + c4];
        a1v = *(const float4*)&g_qf[(row0 + r0 + 64) * 64 + c4];
        u0  = *(const float4*)&g_kf[(row0 + r0) * 64 + c4];
        u1  = *(const float4*)&g_kf[(row0 + r0 + 64) * 64 + c4];
        *(float4*)&As[0][r0][c4] = a0v;
        *(float4*)&As[0][r0+64][c4] = a1v;
        *(float4*)&Ks[0][r0][c4] = u0;
        *(float4*)&Ks[0][r0+64][c4] = u1;
        __syncthreads();

        for (int s = 0; s < 4; s++) {
            int cur = s & 1;
            if (s < 3) {
                int kn = (s + 1) * 16;
                a0v = *(const float4*)&g_qf[(row0 + r0) * 64 + kn + c4];
                a1v = *(const float4*)&g_qf[(row0 + r0 + 64) * 64 + kn + c4];
                u0  = *(const float4*)&g_kf[(row0 + r0) * 64 + kn + c4];
                u1  = *(const float4*)&g_kf[(row0 + r0 + 64) * 64 + kn + c4];
            }
            #pragma unroll
            for (int ks = 0; ks < 2; ks++) {
                unsigned a[2][4];
                #pragma unroll
                for (int mt = 0; mt < 2; mt++) {
                    int rr = wm + mt*16 + lq;
                    int cc = ks*8 + lr;
                    a[mt][0] = __float_as_uint(As[cur][rr][cc]);
                    a[mt][1] = __float_as_uint(As[cur][rr+8][cc]);
                    a[mt][2] = __float_as_uint(As[cur][rr][cc+4]);
                    a[mt][3] = __float_as_uint(As[cur][rr+8][cc+4]);
                }
                #pragma unroll
                for (int nt = 0; nt < 8; nt++) {
                    int bn = wn + nt*8 + lq;
                    unsigned b0 = __float_as_uint(Ks[cur][bn][ks*8+lr]);
                    unsigned b1 = __float_as_uint(Ks[cur][bn][ks*8+lr+4]);
                    #pragma unroll
                    for (int mt = 0; mt < 2; mt++)
                        mma_tf32(acc[mt][nt], a[mt][0], a[mt][1], a[mt][2], a[mt][3], b0, b1);
                }
            }
            if (s < 3) {
                int nb = cur ^ 1;
                *(float4*)&As[nb][r0][c4] = a0v;
                *(float4*)&As[nb][r0+64][c4] = a1v;
                *(float4*)&Ks[nb][r0][c4] = u0;
                *(float4*)&Ks[nb][r0+64][c4] = u1;
            }
            __syncthreads();
        }
        int sb = bc * CC * CC;
        #pragma unroll
        for (int mt = 0; mt < 2; mt++) {
            #pragma unroll
            for (int nt = 0; nt < 8; nt++) {
                int la = wm + mt*16 + lq;
                int lb = la + 8;
                int j0 = wn + nt*8 + lr*2;
                int j1 = j0 + 1;
                *(float2*)&g_scores[sb + la*128 + j0] =
                    make_float2(j0 <= la ? acc[mt][nt][0] : 0.f, j1 <= la ? acc[mt][nt][1] : 0.f);
                *(float2*)&g_scores[sb + lb*128 + j0] =
                    make_float2(j0 <= lb ? acc[mt][nt][2] : 0.f, j1 <= lb ? acc[mt][nt][3] : 0.f);
            }
        }
    }
}

// ======= Kernel 4: content exclusive prefix, 2 threads/chain (shfl handoff) ==========
__global__ __launch_bounds__(256) void k4_prefix()
{
    int tid = threadIdx.x;
    int idx = blockIdx.x * 128 + (tid >> 1);
    int half = tid & 1;
    int b = idx >> 14, rd = idx & 16383;
    float v[8];
    #pragma unroll
    for (int j = 0; j < 8; j++)
        v[j] = g_S[(b * 16 + half * 8 + j) * 16384 + rd];
    float sum = ((v[0]+v[1]) + (v[2]+v[3])) + ((v[4]+v[5]) + (v[6]+v[7]));
    float other = __shfl_xor_sync(~0u, sum, 1);
    float run = half ? other : 0.f;
    #pragma unroll
    for (int j = 0; j < 8; j++) {
        g_P[(b * 16 + half * 8 + j) * 16384 + rd] = run;
        run += v[j];
    }
}

// ================= Kernel 6: content output (3-stage cp.async, 64-wide d) =============
__global__ __launch_bounds__(256) void k6_mma()
{
    __shared__ __align__(16) float As[3][128][20];
    __shared__ __align__(16) float Bs[3][16][68];
    int bc = blockIdx.x; int b = bc >> 4, c = bc & 15;
    int d0 = blockIdx.y * 64;
    int row0 = b * LL + c * CC;
    int tid = threadIdx.x;
    int w = tid >> 5, lane = tid & 31;
    int wm = (w & 3) * 32;
    int wn = (w >> 2) * 32;
    int lq = lane >> 2, lr = lane & 3;
    int r0 = tid >> 2, c4 = (tid & 3) * 4;
    int br = tid >> 4, bc4 = (tid & 15) * 4;
    int Pbase = bc * 64 * 256;
    int sbase = bc * CC * CC;
    float acc[2][4][4] = {};

    #pragma unroll
    for (int p = 0; p < 2; p++) {
        int k0 = p * 16;
        int kga = k0 + c4;
        const float *sa0, *sa1;
        if (kga < 64) {
            sa0 = &g_qf[(row0 + r0) * 64 + kga];
            sa1 = &g_qf[(row0 + r0 + 64) * 64 + kga];
        } else {
            sa0 = &g_scores[sbase + r0 * 128 + kga - 64];
            sa1 = &g_scores[sbase + (r0 + 64) * 128 + kga - 64];
        }
        int kgb = k0 + br;
        const float* sbp = (kgb < 64) ? &g_P[Pbase + kgb * 256 + d0 + bc4]
                                      : &g_vc[(row0 + kgb - 64) * 256 + d0 + bc4];
        cp_async16(&As[p][r0][c4], sa0);
        cp_async16(&As[p][r0+64][c4], sa1);
        cp_async16(&Bs[p][br][bc4], sbp);
        cp_commit();
    }

    for (int s = 0; s < 12; s++) {
        if (s < 11) cp_wait1(); else cp_wait0();
        __syncthreads();
        int cur = s % 3;
        #pragma unroll
        for (int ks = 0; ks < 2; ks++) {
            unsigned a[2][4];
            #pragma unroll
            for (int mt = 0; mt < 2; mt++) {
                int rr = wm + mt*16 + lq;
                int cc = ks*8 + lr;
                a[mt][0] = __float_as_uint(As[cur][rr][cc]);
                a[mt][1] = __float_as_uint(As[cur][rr+8][cc]);
                a[mt][2] = __float_as_uint(As[cur][rr][cc+4]);
                a[mt][3] = __float_as_uint(As[cur][rr+8][cc+4]);
            }
            #pragma unroll
            for (int nt = 0; nt < 4; nt++) {
                int bn = wn + nt*8 + lq;
                unsigned b0 = __float_as_uint(Bs[cur][ks*8+lr][bn]);
                unsigned b1 = __float_as_uint(Bs[cur][ks*8+lr+4][bn]);
                #pragma unroll
                for (int mt = 0; mt < 2; mt++)
                    mma_tf32(acc[mt][nt], a[mt][0], a[mt][1], a[mt][2], a[mt][3], b0, b1);
            }
        }
        if (s < 10) {
            int st = (s + 2) % 3;
            int k0 = (s + 2) * 16;
            int kga = k0 + c4;
            const float *sa0, *sa1;
            if (kga < 64) {
                sa0 = &g_qf[(row0 + r0) * 64 + kga];
                sa1 = &g_qf[(row0 + r0 + 64) * 64 + kga];
            } else {
                sa0 = &g_scores[sbase + r0 * 128 + kga - 64];
                sa1 = &g_scores[sbase + (r0 + 64) * 128 + kga - 64];
            }
            int kgb = k0 + br;
            const float* sbp = (kgb < 64) ? &g_P[Pbase + kgb * 256 + d0 + bc4]
                                          : &g_vc[(row0 + kgb - 64) * 256 + d0 + bc4];
            cp_async16(&As[st][r0][c4], sa0);
            cp_async16(&As[st][r0+64][c4], sa1);
            cp_async16(&Bs[st][br][bc4], sbp);
            cp_commit();
        }
    }
    #pragma unroll
    for (int mt = 0; mt < 2; mt++) {
        #pragma unroll
        for (int nt = 0; nt < 4; nt++) {
            int la = wm + mt*16 + lq;
            int lb = la + 8;
            int cc = d0 + wn + nt*8 + lr*2;
            float sa = rsqrtf((float)((c*CC + la + 1) * KK));
            float sb2 = rsqrtf((float)((c*CC + lb + 1) * KK));
            *(float2*)&g_cont[(row0 + la) * 256 + cc] =
                make_float2(acc[mt][nt][0] * sa, acc[mt][nt][1] * sa);
            *(float2*)&g_cont[(row0 + lb) * 256 + cc] =
                make_float2(acc[mt][nt][2] * sb2, acc[mt][nt][3] * sb2);
        }
    }
}

// ======== Kernel 7: pos scan (cached sincos) + gate combine + LayerNorm =========
__global__ __launch_bounds__(256) void k7_poscomb(
    const float* __restrict__ ln_g, const float* __restrict__ ln_b)
{
    __shared__ float comb[8][257];
    int blk = blockIdx.x;
    int j = blk & 3;
    int s = (blk >> 2) & 63;
    int b = blk >> 8;
    int row0 = b * LL + s * 32 + j * 8;
    int l0 = s * 32 + j * 8;
    int d = threadIdx.x;
    float ar = g_pprefix[(b * 64 + s) * 512 + d];
    float ai = g_pprefix[(b * 64 + s) * 512 + 256 + d];
    if (j > 0) {
        int snapbase = ((b * 64 + s) * 4 + j - 1) * 512;
        ar += g_psnap[snapbase + d];
        ai += g_psnap[snapbase + 256 + d];
    }
    float vp[8], cph[8], sph[8], cv[8];
    #pragma unroll
    for (int lt = 0; lt < 8; lt++) {
        vp[lt]  = g_vp[(row0 + lt) * 256 + d];
        cph[lt] = g_cph[(l0 + lt) * 256 + d];
        sph[lt] = g_sph[(l0 + lt) * 256 + d];
        cv[lt]  = g_cont[(row0 + lt) * 256 + d];
    }
    #pragma unroll
    for (int lt = 0; lt < 8; lt++) {
        ar += vp[lt] * cph[lt]; ai += vp[lt] * sph[lt];
        float pret = (ar * cph[lt] + ai * sph[lt]) * rsqrtf((float)(l0 + lt + 1));
        float g0 = g_gates[(row0 + lt) * 2], g1v = g_gates[(row0 + lt) * 2 + 1];
        comb[lt][d] = g0 * pret + g1v * cv[lt];
    }
    __syncthreads();
    int w = d >> 5, lane = d & 31;
    int r = row0 + w;
    float vals[8]; float s1 = 0.f, s2 = 0.f;
    #pragma unroll
    for (int k = 0; k < 8; k++) {
        float v = comb[w][lane + 32*k];
        vals[k] = v; s1 += v; s2 += v*v;
    }
    #pragma unroll
    for (int off = 16; off; off >>= 1) {
        s1 += __shfl_xor_sync(~0u, s1, off);
        s2 += __shfl_xor_sync(~0u, s2, off);
    }
    float mu = s1 * (1.f/256.f);
    float var = s2 * (1.f/256.f) - mu*mu;
    float rstd = rsqrtf(var + 1e-5f);
    #pragma unroll
    for (int k = 0; k < 8; k++) {
        int dd = lane + 32*k;
        g_norm[r*256 + dd] = (vals[k] - mu) * rstd * ln_g[dd] + ln_b[dd];
    }
}

// ================= Kernel 8: out = x + normed @ Wo + bo (3-stage, 64-wide N) ==========
__global__ __launch_bounds__(256) void k8_mma(
    const float* __restrict__ x, const float* __restrict__ Wo,
    const float* __restrict__ bo, float* __restrict__ out)
{
    __shared__ __align__(16) float As[3][128][20];
    __shared__ __align__(16) float Bs[3][16][68];
    int row0 = blockIdx.x * 128;
    int colbase = blockIdx.y * 64;
    int tid = threadIdx.x;
    int w = tid >> 5, lane = tid & 31;
    int wm = (w & 3) * 32;
    int wn = (w >> 2) * 32;
    int lq = lane >> 2, lr = lane & 3;
    int r0 = tid >> 2, c4 = (tid & 3) * 4;
    int br = tid >> 4, bc4 = (tid & 15) * 4;
    float c[2][4][4] = {};

    #pragma unroll
    for (int p = 0; p < 2; p++) {
        int k0 = p * 16;
        cp_async16(&As[p][r0][c4],    &g_norm[(row0 + r0) * 256 + k0 + c4]);
        cp_async16(&As[p][r0+64][c4], &g_norm[(row0 + r0 + 64) * 256 + k0 + c4]);
        cp_async16(&Bs[p][br][bc4],   &Wo[(k0 + br) * 256 + colbase + bc4]);
        cp_commit();
    }

    for (int s = 0; s < 16; s++) {
        if (s < 15) cp_wait1(); else cp_wait0();
        __syncthreads();
        int cur = s % 3;
        #pragma unroll
        for (int ks = 0; ks < 2; ks++) {
            unsigned a[2][4];
            #pragma unroll
            for (int mt = 0; mt < 2; mt++) {
                int rr = wm + mt*16 + lq;
                int cc = ks*8 + lr;
                a[mt][0] = __float_as_uint(As[cur][rr][cc]);
                a[mt][1] = __float_as_uint(As[cur][rr+8][cc]);
                a[mt][2] = __float_as_uint(As[cur][rr][cc+4]);
                a[mt][3] = __float_as_uint(As[cur][rr+8][cc+4]);
            }
            #pragma unroll
            for (int nt = 0; nt < 4; nt++) {
                int bn = wn + nt*8 + lq;
                unsigned b0 = __float_as_uint(Bs[cur][ks*8+lr][bn]);
                unsigned b1 = __float_as_uint(Bs[cur][ks*8+lr+4][bn]);
                #pragma unroll
                for (int mt = 0; mt < 2; mt++)
                    mma_tf32(c[mt][nt], a[mt][0], a[mt][1], a[mt][2], a[mt][3], b0, b1);
            }
        }
        if (s < 14) {
            int st = (s + 2) % 3;
            int k0 = (s + 2) * 16;
            cp_async16(&As[st][r0][c4],    &g_norm[(row0 + r0) * 256 + k0 + c4]);
            cp_async16(&As[st][r0+64][c4], &g_norm[(row0 + r0 + 64) * 256 + k0 + c4]);
            cp_async16(&Bs[st][br][bc4],   &Wo[(k0 + br) * 256 + colbase + bc4]);
            cp_commit();
        }
    }
    #pragma unroll
    for (int mt = 0; mt < 2; mt++) {
        #pragma unroll
        for (int nt = 0; nt < 4; nt++) {
            int r = row0 + wm + mt*16 + lq;
            int cc = colbase + wn + nt*8 + lr*2;
            float b0v = bo[cc], b1v = bo[cc+1];
            float2 x0 = *(const float2*)&x[r * 256 + cc];
            float2 x1 = *(const float2*)&x[(r+8) * 256 + cc];
            *(float2*)&out[r * 256 + cc] =
                make_float2(c[mt][nt][0] + b0v + x0.x, c[mt][nt][1] + b1v + x0.y);
            *(float2*)&out[(r+8) * 256 + cc] =
                make_float2(c[mt][nt][2] + b0v + x1.x, c[mt][nt][3] + b1v + x1.y);
        }
    }
}

// ================= launcher =================
extern "C" void kernel_launch(void* const* d_in, const int* in_sizes, int n_in,
                              void* d_out, int out_size)
{
    const float* x   = (const float*)d_in[0];
    const float* bp  = (const float*)d_in[1];
    const float* Wk1 = (const float*)d_in[2];
    const float* bk1 = (const float*)d_in[3];
    const float* Wk2 = (const float*)d_in[4];
    const float* bk2 = (const float*)d_in[5];
    const float* Wq1 = (const float*)d_in[6];
    const float* bq1 = (const float*)d_in[7];
    const float* Wq2 = (const float*)d_in[8];
    const float* bq2 = (const float*)d_in[9];
    const float* Wvc = (const float*)d_in[10];
    const float* bvc = (const float*)d_in[11];
    const float* Wvp = (const float*)d_in[12];
    const float* bvp = (const float*)d_in[13];
    const float* Wg1 = (const float*)d_in[14];
    const float* bg1 = (const float*)d_in[15];
    const float* Wg2 = (const float*)d_in[16];
    const float* bg2 = (const float*)d_in[17];
    const float* lng = (const float*)d_in[18];
    const float* lnb = (const float*)d_in[19];
    const float* Wo  = (const float*)d_in[20];
    const float* bo  = (const float*)d_in[21];
    float* out = (float*)d_out;

    cudaFuncSetAttribute(k1_mma, cudaFuncAttributeMaxDynamicSharedMemorySize, 57344);
    k1_mma<<<dim3(32, 9), 256, 56064>>>(x, Wk1, bk1, Wq1, bq1, Wvc, bvc, Wvp, bvp, Wg1, bg1);
    k23b_mma<<<128, 256>>>(Wk2, bk2, Wq2, bq2, Wg2, bg2, bp);
    k3a5_mma<<<100, 256>>>();
    k4_prefix<<<256, 256>>>();
    k6_mma<<<dim3(32, 4), 256>>>();
    k7_poscomb<<<512, 256>>>(lng, lnb);
    k8_mma<<<dim3(32, 4), 256>>>(x, Wo, bo, out);
}

// round 17
// speedup vs baseline: 1.1438x; 1.0345x over previous
#include <cuda_runtime.h>
#include <cuda_bf16.h>
#include <math.h>

// Problem constants
#define Bb 2
#define LL 2048
#define DD 256
#define KK 32
#define FF 64          // 2*K feature dim
#define MM (Bb*LL)     // 4096 rows
#define CC 128         // chunk size
#define NC (LL/CC)     // 16 chunks per batch
#define PI_F 3.14159265358979323846f

// ---------------- scratch (device globals; no allocation allowed) ----------------
__device__ float g_hk[MM*DD];
__device__ float g_hq[MM*DD];
__device__ float g_vc[MM*DD];
__device__ float g_vp[MM*DD];
__device__ float g_g1[MM*64];
__device__ float g_kf[MM*FF];
__device__ float g_qf[MM*FF];
__device__ float g_gates[MM*2];
__device__ float g_S[Bb*NC*FF*DD];         // per-chunk content state sums (mma)
__device__ float g_P[Bb*NC*FF*DD];         // chunk-level exclusive prefix of states
__device__ float g_psnap[Bb*64*4*2*DD];    // pos accum snapshots every 8 rows (inclusive)
__device__ float g_pprefix[Bb*64*2*DD];    // exclusive prefix at 32-row granularity
__device__ float g_scores[Bb*NC*CC*CC];    // intra-chunk masked scores
__device__ float g_cont[MM*DD];
__device__ float g_norm[MM*DD];
__device__ float g_cph[LL*DD];             // cached cos(base_phases[:LL])
__device__ float g_sph[LL*DD];             // cached sin(base_phases[:LL])

// ---------------- PDL (programmatic dependent launch) ----------------
#define GDC_WAIT()   asm volatile("griddepcontrol.wait;" ::: "memory")
#define GDC_LAUNCH() asm volatile("griddepcontrol.launch_dependents;" ::: "memory")

// mma consumes raw f32 bit patterns as tf32 (HW truncates mantissa; no cvt needed)
__device__ __forceinline__ void mma_tf32(float c[4],
    unsigned a0, unsigned a1, unsigned a2, unsigned a3,
    unsigned b0, unsigned b1)
{
    asm volatile(
        "mma.sync.aligned.m16n8k8.row.col.f32.tf32.tf32.f32 "
        "{%0,%1,%2,%3}, {%4,%5,%6,%7}, {%8,%9}, {%0,%1,%2,%3};"
        : "+f"(c[0]), "+f"(c[1]), "+f"(c[2]), "+f"(c[3])
        : "r"(a0), "r"(a1), "r"(a2), "r"(a3), "r"(b0), "r"(b1));
}

// ---------------- cp.async helpers ----------------
__device__ __forceinline__ void cp_async16(void* smem_dst, const void* gsrc) {
    unsigned saddr = (unsigned)__cvta_generic_to_shared(smem_dst);
    asm volatile("cp.async.cg.shared.global [%0], [%1], 16;" :: "r"(saddr), "l"(gsrc));
}
__device__ __forceinline__ void cp_commit() {
    asm volatile("cp.async.commit_group;");
}
__device__ __forceinline__ void cp_wait1() {
    asm volatile("cp.async.wait_group 1;");
}
__device__ __forceinline__ void cp_wait0() {
    asm volatile("cp.async.wait_group 0;");
}

// ================= Kernel 1: fused first-layer GEMMs, 128x128 tiles (3-stage) =========
// grid (32, 9): ct<8 -> [hk|hq|vc|vp] x 2 col-halves; ct==8 -> g1 (64 cols, predicated)
__global__ __launch_bounds__(256) void k1_mma(
    const float* __restrict__ x,
    const float* __restrict__ Wk1, const float* __restrict__ bk1,
    const float* __restrict__ Wq1, const float* __restrict__ bq1,
    const float* __restrict__ Wvc, const float* __restrict__ bvc,
    const float* __restrict__ Wvp, const float* __restrict__ bvp,
    const float* __restrict__ Wg1, const float* __restrict__ bg1)
{
    extern __shared__ __align__(16) float smem[];
    float (*As)[128][20] = (float(*)[128][20])smem;            // 3*2560 floats
    float (*Bs)[16][132] = (float(*)[16][132])(smem + 7680);   // 3*2112 floats
    int ct = blockIdx.y;
    const float* W; const float* bias; float* outp; int Nseg; int act; int colbase;
    if (ct < 8) {
        int seg = ct >> 1;
        colbase = (ct & 1) * 128;
        Nseg = 256;
        if (seg == 0)      { W = Wk1; bias = bk1; outp = g_hk; act = 1; }
        else if (seg == 1) { W = Wq1; bias = bq1; outp = g_hq; act = 1; }
        else if (seg == 2) { W = Wvc; bias = bvc; outp = g_vc; act = 0; }
        else               { W = Wvp; bias = bvp; outp = g_vp; act = 0; }
    } else {
        W = Wg1; bias = bg1; outp = g_g1; Nseg = 64; act = 2; colbase = 0;
    }
    int row0 = blockIdx.x * 128;
    int tid = threadIdx.x;
    int w = tid >> 5, lane = tid & 31;
    int wm = (w & 3) * 32;
    int wn = (w >> 2) * 64;
    int lq = lane >> 2, lr = lane & 3;
    int r0 = tid >> 2, c4 = (tid & 3) * 4;
    int rB = tid >> 5, cB = (tid & 31) * 4;
    bool bok = (colbase + cB) < Nseg;
    float c[2][8][4] = {};

    #pragma unroll
    for (int p = 0; p < 2; p++) {
        int k0 = p * 16;
        cp_async16(&As[p][r0][c4],    &x[(row0 + r0) * 256 + k0 + c4]);
        cp_async16(&As[p][r0+64][c4], &x[(row0 + r0 + 64) * 256 + k0 + c4]);
        if (bok) {
            cp_async16(&Bs[p][rB][cB],   &W[(k0 + rB) * Nseg + colbase + cB]);
            cp_async16(&Bs[p][rB+8][cB], &W[(k0 + rB + 8) * Nseg + colbase + cB]);
        }
        cp_commit();
    }

    for (int s = 0; s < 16; s++) {
        if (s < 15) cp_wait1(); else cp_wait0();
        __syncthreads();
        int cur = s % 3;
        #pragma unroll
        for (int ks = 0; ks < 2; ks++) {
            unsigned a[2][4];
            #pragma unroll
            for (int mt = 0; mt < 2; mt++) {
                int rr = wm + mt*16 + lq;
                int cc = ks*8 + lr;
                a[mt][0] = __float_as_uint(As[cur][rr][cc]);
                a[mt][1] = __float_as_uint(As[cur][rr+8][cc]);
                a[mt][2] = __float_as_uint(As[cur][rr][cc+4]);
                a[mt][3] = __float_as_uint(As[cur][rr+8][cc+4]);
            }
            #pragma unroll
            for (int nt = 0; nt < 8; nt++) {
                int bn = wn + nt*8 + lq;
                unsigned b0 = __float_as_uint(Bs[cur][ks*8+lr][bn]);
                unsigned b1 = __float_as_uint(Bs[cur][ks*8+lr+4][bn]);
                #pragma unroll
                for (int mt = 0; mt < 2; mt++)
                    mma_tf32(c[mt][nt], a[mt][0], a[mt][1], a[mt][2], a[mt][3], b0, b1);
            }
        }
        if (s < 14) {
            int st = (s + 2) % 3;
            int k0 = (s + 2) * 16;
            cp_async16(&As[st][r0][c4],    &x[(row0 + r0) * 256 + k0 + c4]);
            cp_async16(&As[st][r0+64][c4], &x[(row0 + r0 + 64) * 256 + k0 + c4]);
            if (bok) {
                cp_async16(&Bs[st][rB][cB],   &W[(k0 + rB) * Nseg + colbase + cB]);
                cp_async16(&Bs[st][rB+8][cB], &W[(k0 + rB + 8) * Nseg + colbase + cB]);
            }
            cp_commit();
        }
    }
    #pragma unroll
    for (int mt = 0; mt < 2; mt++) {
        #pragma unroll
        for (int nt = 0; nt < 8; nt++) {
            int cc = colbase + wn + nt*8 + lr*2;
            if (cc < Nseg) {
                int r = row0 + wm + mt*16 + lq;
                float b0v = bias[cc], b1v = bias[cc+1];
                float v00 = c[mt][nt][0] + b0v, v01 = c[mt][nt][1] + b1v;
                float v10 = c[mt][nt][2] + b0v, v11 = c[mt][nt][3] + b1v;
                if (act == 1) { v00 = tanhf(v00); v01 = tanhf(v01); v10 = tanhf(v10); v11 = tanhf(v11); }
                else if (act == 2) { v00 = fmaxf(v00,0.f); v01 = fmaxf(v01,0.f); v10 = fmaxf(v10,0.f); v11 = fmaxf(v11,0.f); }
                *(float2*)&outp[r * Nseg + cc] = make_float2(v00, v01);
                *(float2*)&outp[(r+8) * Nseg + cc] = make_float2(v10, v11);
            }
        }
    }
    GDC_LAUNCH();
}

// ===== Kernel 2+3b merged: split phase GEMMs (3-stage cp.async) || pos partials =======
__global__ __launch_bounds__(256) void k23b_mma(
    const float* __restrict__ Wk2, const float* __restrict__ bk2,
    const float* __restrict__ Wq2, const float* __restrict__ bq2,
    const float* __restrict__ Wg2, const float* __restrict__ bg2,
    const float* __restrict__ base_phases)
{
    __shared__ __align__(16) float As[3][128][20];
    __shared__ __align__(16) float Bs[3][16][36];
    int tid = threadIdx.x;
    int bx = blockIdx.x;
    GDC_WAIT();

    if (bx >= 64) {
        int s = bx - 64;            // 0..63
        int l0 = s * 32;
        int row0_0 = l0;            // b = 0
        int row0_1 = LL + l0;       // b = 1
        int d = tid;
        float par0 = 0.f, pai0 = 0.f, par1 = 0.f, pai1 = 0.f;
        #pragma unroll
        for (int g = 0; g < 4; g++) {
            float ph8[8], v0[8], v1[8];
            #pragma unroll
            for (int j = 0; j < 8; j++) {
                ph8[j] = base_phases[(l0 + g*8 + j) * 256 + d];
                v0[j] = g_vp[(row0_0 + g*8 + j) * 256 + d];
                v1[j] = g_vp[(row0_1 + g*8 + j) * 256 + d];
            }
            #pragma unroll
            for (int j = 0; j < 8; j++) {
                float sp, cp; __sincosf(ph8[j], &sp, &cp);
                int l = l0 + g*8 + j;
                g_cph[l*256 + d] = cp;
                g_sph[l*256 + d] = sp;
                par0 += v0[j] * cp; pai0 += v0[j] * sp;
                par1 += v1[j] * cp; pai1 += v1[j] * sp;
            }
            int sb0 = (s * 4 + g) * 512;
            int sb1 = ((64 + s) * 4 + g) * 512;
            g_psnap[sb0 + d] = par0; g_psnap[sb0 + 256 + d] = pai0;
            g_psnap[sb1 + d] = par1; g_psnap[sb1 + 256 + d] = pai1;
        }
        GDC_LAUNCH();
        return;
    }

    bool isq = (bx >= 32);
    int row0 = (bx & 31) * 128;
    const float* H  = isq ? g_hq : g_hk;
    const float* W2 = isq ? Wq2 : Wk2;
    const float* bvec = isq ? bq2 : bk2;
    float* fdst = isq ? g_qf : g_kf;

    int w = tid >> 5, lane = tid & 31;
    int wm = (w & 3) * 32;
    int wn = (w >> 2) * 16;
    int lq = lane >> 2, lr = lane & 3;
    int r0 = tid >> 2, c4 = (tid & 3) * 4;
    int brB = tid >> 3, bc4B = (tid & 7) * 4;   // valid for tid < 128
    float c[2][2][4] = {};

    #pragma unroll
    for (int p = 0; p < 2; p++) {
        int k0 = p * 16;
        cp_async16(&As[p][r0][c4],    &H[(row0 + r0) * 256 + k0 + c4]);
        cp_async16(&As[p][r0+64][c4], &H[(row0 + r0 + 64) * 256 + k0 + c4]);
        if (tid < 128)
            cp_async16(&Bs[p][brB][bc4B], &W2[(k0 + brB) * 32 + bc4B]);
        cp_commit();
    }

    for (int s = 0; s < 16; s++) {
        if (s < 15) cp_wait1(); else cp_wait0();
        __syncthreads();
        int cur = s % 3;
        #pragma unroll
        for (int ks = 0; ks < 2; ks++) {
            unsigned a[2][4];
            #pragma unroll
            for (int mt = 0; mt < 2; mt++) {
                int rr = wm + mt*16 + lq;
                int cc = ks*8 + lr;
                a[mt][0] = __float_as_uint(As[cur][rr][cc]);
                a[mt][1] = __float_as_uint(As[cur][rr+8][cc]);
                a[mt][2] = __float_as_uint(As[cur][rr][cc+4]);
                a[mt][3] = __float_as_uint(As[cur][rr+8][cc+4]);
            }
            #pragma unroll
            for (int nt = 0; nt < 2; nt++) {
                int bn = wn + nt*8 + lq;
                unsigned b0 = __float_as_uint(Bs[cur][ks*8+lr][bn]);
                unsigned b1 = __float_as_uint(Bs[cur][ks*8+lr+4][bn]);
                #pragma unroll
                for (int mt = 0; mt < 2; mt++)
                    mma_tf32(c[mt][nt], a[mt][0], a[mt][1], a[mt][2], a[mt][3], b0, b1);
            }
        }
        if (s < 14) {
            int st = (s + 2) % 3;
            int k0 = (s + 2) * 16;
            cp_async16(&As[st][r0][c4],    &H[(row0 + r0) * 256 + k0 + c4]);
            cp_async16(&As[st][r0+64][c4], &H[(row0 + r0 + 64) * 256 + k0 + c4]);
            if (tid < 128)
                cp_async16(&Bs[st][brB][bc4B], &W2[(k0 + brB) * 32 + bc4B]);
            cp_commit();
        }
    }

    #pragma unroll
    for (int mt = 0; mt < 2; mt++) {
        #pragma unroll
        for (int nt = 0; nt < 2; nt++) {
            int r = row0 + wm + mt*16 + lq;
            int cn = wn + nt*8 + lr*2;
            float b0v = bvec[cn], b1v = bvec[cn+1];
            float ph;
            float sp, cp;
            ph = tanhf(c[mt][nt][0] + b0v) * PI_F; __sincosf(ph, &sp, &cp);
            fdst[r*64 + cn] = cp; fdst[r*64 + 32 + cn] = sp;
            ph = tanhf(c[mt][nt][1] + b1v) * PI_F; __sincosf(ph, &sp, &cp);
            fdst[r*64 + cn+1] = cp; fdst[r*64 + 32 + cn+1] = sp;
            ph = tanhf(c[mt][nt][2] + b0v) * PI_F; __sincosf(ph, &sp, &cp);
            fdst[(r+8)*64 + cn] = cp; fdst[(r+8)*64 + 32 + cn] = sp;
            ph = tanhf(c[mt][nt][3] + b1v) * PI_F; __sincosf(ph, &sp, &cp);
            fdst[(r+8)*64 + cn+1] = cp; fdst[(r+8)*64 + 32 + cn+1] = sp;
        }
    }
    // gates only in the k-path blocks
    if (!isq) {
        for (int rr = 0; rr < 16; rr++) {
            int r = row0 + w*16 + rr;
            float p0 = 0.f, p1 = 0.f;
            #pragma unroll
            for (int i = lane; i < 64; i += 32) {
                float gv = g_g1[r*64 + i];
                p0 += gv * Wg2[i*2 + 0];
                p1 += gv * Wg2[i*2 + 1];
            }
            #pragma unroll
            for (int off = 16; off; off >>= 1) {
                p0 += __shfl_xor_sync(~0u, p0, off);
                p1 += __shfl_xor_sync(~0u, p1, off);
            }
            if (lane == 0) {
                float l0 = p0 + bg2[0], l1 = p1 + bg2[1];
                float m = fmaxf(l0, l1);
                float e0 = __expf(l0 - m), e1 = __expf(l1 - m);
                float inv = 1.f / (e0 + e1);
                g_gates[r*2 + 0] = e0 * inv;
                g_gates[r*2 + 1] = e1 * inv;
            }
        }
    }
    GDC_LAUNCH();
}

// ======== Kernel 3a+5 merged (+ pos prefix): chunk states || scores || pos-scan =======
__global__ __launch_bounds__(256) void k3a5_mma()
{
    __shared__ float sraw[10240];
    int tid = threadIdx.x;
    int w = tid >> 5, lane = tid & 31;
    int lq = lane >> 2, lr = lane & 3;
    GDC_WAIT();

    if (blockIdx.x >= 96) {
        int e = (blockIdx.x - 96) * 256 + tid;
        if (e < 1024) {
            int b = e >> 9, rd = e & 511;
            float v[64];
            #pragma unroll
            for (int s = 0; s < 64; s++)
                v[s] = g_psnap[((b * 64 + s) * 4 + 3) * 512 + rd];
            float run = 0.f;
            #pragma unroll
            for (int s = 0; s < 64; s++) {
                g_pprefix[(b * 64 + s) * 512 + rd] = run;
                run += v[s];
            }
        }
        GDC_LAUNCH();
        return;
    }

    if (blockIdx.x < 64) {
        float (*Kl)[16][68]  = (float(*)[16][68])sraw;
        float (*Bs)[16][132] = (float(*)[16][132])(sraw + 2176);
        int bc = blockIdx.x & 31;
        int b = bc >> 4, c = bc & 15;
        int d0 = (blockIdx.x >> 5) * 128;
        int row0 = b * LL + c * CC;
        int wm = (w & 1) * 32, wn = (w >> 1) * 32;
        int af4 = (tid & 15) * 4, al = tid >> 4;
        int rB = tid >> 5, cB = (tid & 31) * 4;
        float acc[2][4][4] = {};
        float4 av, bv0, bv1;

        av  = *(const float4*)&g_kf[(row0 + al) * 64 + af4];
        bv0 = *(const float4*)&g_vc[(row0 + rB) * 256 + d0 + cB];
        bv1 = *(const float4*)&g_vc[(row0 + rB + 8) * 256 + d0 + cB];
        *(float4*)&Kl[0][al][af4] = av;
        *(float4*)&Bs[0][rB][cB] = bv0;
        *(float4*)&Bs[0][rB+8][cB] = bv1;
        __syncthreads();

        for (int s = 0; s < 8; s++) {
            int cur = s & 1;
            if (s < 7) {
                int kn = (s + 1) * 16;
                av  = *(const float4*)&g_kf[(row0 + kn + al) * 64 + af4];
                bv0 = *(const float4*)&g_vc[(row0 + kn + rB) * 256 + d0 + cB];
                bv1 = *(const float4*)&g_vc[(row0 + kn + rB + 8) * 256 + d0 + cB];
            }
            #pragma unroll
            for (int ks = 0; ks < 2; ks++) {
                unsigned a[2][4];
                #pragma unroll
                for (int mt = 0; mt < 2; mt++) {
                    int rr = wm + mt*16 + lq;
                    int cc = ks*8 + lr;
                    a[mt][0] = __float_as_uint(Kl[cur][cc][rr]);
                    a[mt][1] = __float_as_uint(Kl[cur][cc][rr+8]);
                    a[mt][2] = __float_as_uint(Kl[cur][cc+4][rr]);
                    a[mt][3] = __float_as_uint(Kl[cur][cc+4][rr+8]);
                }
                #pragma unroll
                for (int nt = 0; nt < 4; nt++) {
                    int bn = wn + nt*8 + lq;
                    unsigned b0 = __float_as_uint(Bs[cur][ks*8+lr][bn]);
                    unsigned b1 = __float_as_uint(Bs[cur][ks*8+lr+4][bn]);
                    #pragma unroll
                    for (int mt = 0; mt < 2; mt++)
                        mma_tf32(acc[mt][nt], a[mt][0], a[mt][1], a[mt][2], a[mt][3], b0, b1);
                }
            }
            if (s < 7) {
                int nb = cur ^ 1;
                *(float4*)&Kl[nb][al][af4] = av;
                *(float4*)&Bs[nb][rB][cB] = bv0;
                *(float4*)&Bs[nb][rB+8][cB] = bv1;
            }
            __syncthreads();
        }
        int base = bc * 64 * 256;
        #pragma unroll
        for (int mt = 0; mt < 2; mt++) {
            #pragma unroll
            for (int nt = 0; nt < 4; nt++) {
                int f = wm + mt*16 + lq;
                int dd = d0 + wn + nt*8 + lr*2;
                *(float2*)&g_S[base + f * 256 + dd] = make_float2(acc[mt][nt][0], acc[mt][nt][1]);
                *(float2*)&g_S[base + (f+8) * 256 + dd] = make_float2(acc[mt][nt][2], acc[mt][nt][3]);
            }
        }
        GDC_LAUNCH();
        return;
    }

    {
        float (*As)[128][20] = (float(*)[128][20])sraw;
        float (*Ks)[128][20] = (float(*)[128][20])(sraw + 5120);
        int bc = blockIdx.x - 64;
        int b = bc >> 4, c = bc & 15;
        int row0 = b * LL + c * CC;
        int wm = (w & 3) * 32;
        int wn = (w >> 2) * 64;
        int r0 = tid >> 2, c4 = (tid & 3) * 4;
        float acc[2][8][4] = {};
        float4 a0v, a1v, u0, u1;

        a0v = *(const float4*)&g_qf[(row0 + r0) * 64 + c4];
        a1v = *(const float4*)&g_qf[(row0 + r0 + 64) * 64 + c4];
        u0  = *(const float4*)&g_kf[(row0 + r0) * 64 + c4];
        u1  = *(const float4*)&g_kf[(row0 + r0 + 64) * 64 + c4];
        *(float4*)&As[0][r0][c4] = a0v;
        *(float4*)&As[0][r0+64][c4] = a1v;
        *(float4*)&Ks[0][r0][c4] = u0;
        *(float4*)&Ks[0][r0+64][c4] = u1;
        __syncthreads();

        for (int s = 0; s < 4; s++) {
            int cur = s & 1;
            if (s < 3) {
                int kn = (s + 1) * 16;
                a0v = *(const float4*)&g_qf[(row0 + r0) * 64 + kn + c4];
                a1v = *(const float4*)&g_qf[(row0 + r0 + 64) * 64 + kn + c4];
                u0  = *(const float4*)&g_kf[(row0 + r0) * 64 + kn + c4];
                u1  = *(const float4*)&g_kf[(row0 + r0 + 64) * 64 + kn + c4];
            }
            #pragma unroll
            for (int ks = 0; ks < 2; ks++) {
                unsigned a[2][4];
                #pragma unroll
                for (int mt = 0; mt < 2; mt++) {
                    int rr = wm + mt*16 + lq;
                    int cc = ks*8 + lr;
                    a[mt][0] = __float_as_uint(As[cur][rr][cc]);
                    a[mt][1] = __float_as_uint(As[cur][rr+8][cc]);
                    a[mt][2] = __float_as_uint(As[cur][rr][cc+4]);
                    a[mt][3] = __float_as_uint(As[cur][rr+8][cc+4]);
                }
                #pragma unroll
                for (int nt = 0; nt < 8; nt++) {
                    int bn = wn + nt*8 + lq;
                    unsigned b0 = __float_as_uint(Ks[cur][bn][ks*8+lr]);
                    unsigned b1 = __float_as_uint(Ks[cur][bn][ks*8+lr+4]);
                    #pragma unroll
                    for (int mt = 0; mt < 2; mt++)
                        mma_tf32(acc[mt][nt], a[mt][0], a[mt][1], a[mt][2], a[mt][3], b0, b1);
                }
            }
            if (s < 3) {
                int nb = cur ^ 1;
                *(float4*)&As[nb][r0][c4] = a0v;
                *(float4*)&As[nb][r0+64][c4] = a1v;
                *(float4*)&Ks[nb][r0][c4] = u0;
                *(float4*)&Ks[nb][r0+64][c4] = u1;
            }
            __syncthreads();
        }
        int sb = bc * CC * CC;
        #pragma unroll
        for (int mt = 0; mt < 2; mt++) {
            #pragma unroll
            for (int nt = 0; nt < 8; nt++) {
                int la = wm + mt*16 + lq;
                int lb = la + 8;
                int j0 = wn + nt*8 + lr*2;
                int j1 = j0 + 1;
                *(float2*)&g_scores[sb + la*128 + j0] =
                    make_float2(j0 <= la ? acc[mt][nt][0] : 0.f, j1 <= la ? acc[mt][nt][1] : 0.f);
                *(float2*)&g_scores[sb + lb*128 + j0] =
                    make_float2(j0 <= lb ? acc[mt][nt][2] : 0.f, j1 <= lb ? acc[mt][nt][3] : 0.f);
            }
        }
        GDC_LAUNCH();
    }
}

// ======= Kernel 4: content exclusive prefix, 2 threads/chain (shfl handoff) ==========
__global__ __launch_bounds__(256) void k4_prefix()
{
    int tid = threadIdx.x;
    GDC_WAIT();
    int idx = blockIdx.x * 128 + (tid >> 1);
    int half = tid & 1;
    int b = idx >> 14, rd = idx & 16383;
    float v[8];
    #pragma unroll
    for (int j = 0; j < 8; j++)
        v[j] = g_S[(b * 16 + half * 8 + j) * 16384 + rd];
    float sum = ((v[0]+v[1]) + (v[2]+v[3])) + ((v[4]+v[5]) + (v[6]+v[7]));
    float other = __shfl_xor_sync(~0u, sum, 1);
    float run = half ? other : 0.f;
    #pragma unroll
    for (int j = 0; j < 8; j++) {
        g_P[(b * 16 + half * 8 + j) * 16384 + rd] = run;
        run += v[j];
    }
    GDC_LAUNCH();
}

// ================= Kernel 6: content output (3-stage cp.async, 64-wide d) =============
__global__ __launch_bounds__(256) void k6_mma()
{
    __shared__ __align__(16) float As[3][128][20];
    __shared__ __align__(16) float Bs[3][16][68];
    int bc = blockIdx.x; int b = bc >> 4, c = bc & 15;
    int d0 = blockIdx.y * 64;
    int row0 = b * LL + c * CC;
    int tid = threadIdx.x;
    int w = tid >> 5, lane = tid & 31;
    int wm = (w & 3) * 32;
    int wn = (w >> 2) * 32;
    int lq = lane >> 2, lr = lane & 3;
    int r0 = tid >> 2, c4 = (tid & 3) * 4;
    int br = tid >> 4, bc4 = (tid & 15) * 4;
    int Pbase = bc * 64 * 256;
    int sbase = bc * CC * CC;
    float acc[2][4][4] = {};
    GDC_WAIT();

    #pragma unroll
    for (int p = 0; p < 2; p++) {
        int k0 = p * 16;
        int kga = k0 + c4;
        const float *sa0, *sa1;
        if (kga < 64) {
            sa0 = &g_qf[(row0 + r0) * 64 + kga];
            sa1 = &g_qf[(row0 + r0 + 64) * 64 + kga];
        } else {
            sa0 = &g_scores[sbase + r0 * 128 + kga - 64];
            sa1 = &g_scores[sbase + (r0 + 64) * 128 + kga - 64];
        }
        int kgb = k0 + br;
        const float* sbp = (kgb < 64) ? &g_P[Pbase + kgb * 256 + d0 + bc4]
                                      : &g_vc[(row0 + kgb - 64) * 256 + d0 + bc4];
        cp_async16(&As[p][r0][c4], sa0);
        cp_async16(&As[p][r0+64][c4], sa1);
        cp_async16(&Bs[p][br][bc4], sbp);
        cp_commit();
    }

    for (int s = 0; s < 12; s++) {
        if (s < 11) cp_wait1(); else cp_wait0();
        __syncthreads();
        int cur = s % 3;
        #pragma unroll
        for (int ks = 0; ks < 2; ks++) {
            unsigned a[2][4];
            #pragma unroll
            for (int mt = 0; mt < 2; mt++) {
                int rr = wm + mt*16 + lq;
                int cc = ks*8 + lr;
                a[mt][0] = __float_as_uint(As[cur][rr][cc]);
                a[mt][1] = __float_as_uint(As[cur][rr+8][cc]);
                a[mt][2] = __float_as_uint(As[cur][rr][cc+4]);
                a[mt][3] = __float_as_uint(As[cur][rr+8][cc+4]);
            }
            #pragma unroll
            for (int nt = 0; nt < 4; nt++) {
                int bn = wn + nt*8 + lq;
                unsigned b0 = __float_as_uint(Bs[cur][ks*8+lr][bn]);
                unsigned b1 = __float_as_uint(Bs[cur][ks*8+lr+4][bn]);
                #pragma unroll
                for (int mt = 0; mt < 2; mt++)
                    mma_tf32(acc[mt][nt], a[mt][0], a[mt][1], a[mt][2], a[mt][3], b0, b1);
            }
        }
        if (s < 10) {
            int st = (s + 2) % 3;
            int k0 = (s + 2) * 16;
            int kga = k0 + c4;
            const float *sa0, *sa1;
            if (kga < 64) {
                sa0 = &g_qf[(row0 + r0) * 64 + kga];
                sa1 = &g_qf[(row0 + r0 + 64) * 64 + kga];
            } else {
                sa0 = &g_scores[sbase + r0 * 128 + kga - 64];
                sa1 = &g_scores[sbase + (r0 + 64) * 128 + kga - 64];
            }
            int kgb = k0 + br;
            const float* sbp = (kgb < 64) ? &g_P[Pbase + kgb * 256 + d0 + bc4]
                                          : &g_vc[(row0 + kgb - 64) * 256 + d0 + bc4];
            cp_async16(&As[st][r0][c4], sa0);
            cp_async16(&As[st][r0+64][c4], sa1);
            cp_async16(&Bs[st][br][bc4], sbp);
            cp_commit();
        }
    }
    #pragma unroll
    for (int mt = 0; mt < 2; mt++) {
        #pragma unroll
        for (int nt = 0; nt < 4; nt++) {
            int la = wm + mt*16 + lq;
            int lb = la + 8;
            int cc = d0 + wn + nt*8 + lr*2;
            float sa = rsqrtf((float)((c*CC + la + 1) * KK));
            float sb2 = rsqrtf((float)((c*CC + lb + 1) * KK));
            *(float2*)&g_cont[(row0 + la) * 256 + cc] =
                make_float2(acc[mt][nt][0] * sa, acc[mt][nt][1] * sa);
            *(float2*)&g_cont[(row0 + lb) * 256 + cc] =
                make_float2(acc[mt][nt][2] * sb2, acc[mt][nt][3] * sb2);
        }
    }
    GDC_LAUNCH();
}

// ======== Kernel 7: pos scan (cached sincos) + gate combine + LayerNorm =========
__global__ __launch_bounds__(256) void k7_poscomb(
    const float* __restrict__ ln_g, const float* __restrict__ ln_b)
{
    __shared__ float comb[8][257];
    int blk = blockIdx.x;
    int j = blk & 3;
    int s = (blk >> 2) & 63;
    int b = blk >> 8;
    int row0 = b * LL + s * 32 + j * 8;
    int l0 = s * 32 + j * 8;
    int d = threadIdx.x;
    GDC_WAIT();
    float ar = g_pprefix[(b * 64 + s) * 512 + d];
    float ai = g_pprefix[(b * 64 + s) * 512 + 256 + d];
    if (j > 0) {
        int snapbase = ((b * 64 + s) * 4 + j - 1) * 512;
        ar += g_psnap[snapbase + d];
        ai += g_psnap[snapbase + 256 + d];
    }
    float vp[8], cph[8], sph[8], cv[8];
    #pragma unroll
    for (int lt = 0; lt < 8; lt++) {
        vp[lt]  = g_vp[(row0 + lt) * 256 + d];
        cph[lt] = g_cph[(l0 + lt) * 256 + d];
        sph[lt] = g_sph[(l0 + lt) * 256 + d];
        cv[lt]  = g_cont[(row0 + lt) * 256 + d];
    }
    #pragma unroll
    for (int lt = 0; lt < 8; lt++) {
        ar += vp[lt] * cph[lt]; ai += vp[lt] * sph[lt];
        float pret = (ar * cph[lt] + ai * sph[lt]) * rsqrtf((float)(l0 + lt + 1));
        float g0 = g_gates[(row0 + lt) * 2], g1v = g_gates[(row0 + lt) * 2 + 1];
        comb[lt][d] = g0 * pret + g1v * cv[lt];
    }
    __syncthreads();
    int w = d >> 5, lane = d & 31;
    int r = row0 + w;
    float vals[8]; float s1 = 0.f, s2 = 0.f;
    #pragma unroll
    for (int k = 0; k < 8; k++) {
        float v = comb[w][lane + 32*k];
        vals[k] = v; s1 += v; s2 += v*v;
    }
    #pragma unroll
    for (int off = 16; off; off >>= 1) {
        s1 += __shfl_xor_sync(~0u, s1, off);
        s2 += __shfl_xor_sync(~0u, s2, off);
    }
    float mu = s1 * (1.f/256.f);
    float var = s2 * (1.f/256.f) - mu*mu;
    float rstd = rsqrtf(var + 1e-5f);
    #pragma unroll
    for (int k = 0; k < 8; k++) {
        int dd = lane + 32*k;
        g_norm[r*256 + dd] = (vals[k] - mu) * rstd * ln_g[dd] + ln_b[dd];
    }
    GDC_LAUNCH();
}

// ================= Kernel 8: out = x + normed @ Wo + bo (3-stage, 64-wide N) ==========
__global__ __launch_bounds__(256) void k8_mma(
    const float* __restrict__ x, const float* __restrict__ Wo,
    const float* __restrict__ bo, float* __restrict__ out)
{
    __shared__ __align__(16) float As[3][128][20];
    __shared__ __align__(16) float Bs[3][16][68];
    int row0 = blockIdx.x * 128;
    int colbase = blockIdx.y * 64;
    int tid = threadIdx.x;
    int w = tid >> 5, lane = tid & 31;
    int wm = (w & 3) * 32;
    int wn = (w >> 2) * 32;
    int lq = lane >> 2, lr = lane & 3;
    int r0 = tid >> 2, c4 = (tid & 3) * 4;
    int br = tid >> 4, bc4 = (tid & 15) * 4;
    float c[2][4][4] = {};
    GDC_WAIT();

    #pragma unroll
    for (int p = 0; p < 2; p++) {
        int k0 = p * 16;
        cp_async16(&As[p][r0][c4],    &g_norm[(row0 + r0) * 256 + k0 + c4]);
        cp_async16(&As[p][r0+64][c4], &g_norm[(row0 + r0 + 64) * 256 + k0 + c4]);
        cp_async16(&Bs[p][br][bc4],   &Wo[(k0 + br) * 256 + colbase + bc4]);
        cp_commit();
    }

    for (int s = 0; s < 16; s++) {
        if (s < 15) cp_wait1(); else cp_wait0();
        __syncthreads();
        int cur = s % 3;
        #pragma unroll
        for (int ks = 0; ks < 2; ks++) {
            unsigned a[2][4];
            #pragma unroll
            for (int mt = 0; mt < 2; mt++) {
                int rr = wm + mt*16 + lq;
                int cc = ks*8 + lr;
                a[mt][0] = __float_as_uint(As[cur][rr][cc]);
                a[mt][1] = __float_as_uint(As[cur][rr+8][cc]);
                a[mt][2] = __float_as_uint(As[cur][rr][cc+4]);
                a[mt][3] = __float_as_uint(As[cur][rr+8][cc+4]);
            }
            #pragma unroll
            for (int nt = 0; nt < 4; nt++) {
                int bn = wn + nt*8 + lq;
                unsigned b0 = __float_as_uint(Bs[cur][ks*8+lr][bn]);
                unsigned b1 = __float_as_uint(Bs[cur][ks*8+lr+4][bn]);
                #pragma unroll
                for (int mt = 0; mt < 2; mt++)
                    mma_tf32(c[mt][nt], a[mt][0], a[mt][1], a[mt][2], a[mt][3], b0, b1);
            }
        }
        if (s < 14) {
            int st = (s + 2) % 3;
            int k0 = (s + 2) * 16;
            cp_async16(&As[st][r0][c4],    &g_norm[(row0 + r0) * 256 + k0 + c4]);
            cp_async16(&As[st][r0+64][c4], &g_norm[(row0 + r0 + 64) * 256 + k0 + c4]);
            cp_async16(&Bs[st][br][bc4],   &Wo[(k0 + br) * 256 + colbase + bc4]);
            cp_commit();
        }
    }
    #pragma unroll
    for (int mt = 0; mt < 2; mt++) {
        #pragma unroll
        for (int nt = 0; nt < 4; nt++) {
            int r = row0 + wm + mt*16 + lq;
            int cc = colbase + wn + nt*8 + lr*2;
            float b0v = bo[cc], b1v = bo[cc+1];
            float2 x0 = *(const float2*)&x[r * 256 + cc];
            float2 x1 = *(const float2*)&x[(r+8) * 256 + cc];
            *(float2*)&out[r * 256 + cc] =
                make_float2(c[mt][nt][0] + b0v + x0.x, c[mt][nt][1] + b1v + x0.y);
            *(float2*)&out[(r+8) * 256 + cc] =
                make_float2(c[mt][nt][2] + b0v + x1.x, c[mt][nt][3] + b1v + x1.y);
        }
    }
}

// ================= launcher =================
extern "C" void kernel_launch(void* const* d_in, const int* in_sizes, int n_in,
                              void* d_out, int out_size)
{
    const float* x   = (const float*)d_in[0];
    const float* bp  = (const float*)d_in[1];
    const float* Wk1 = (const float*)d_in[2];
    const float* bk1 = (const float*)d_in[3];
    const float* Wk2 = (const float*)d_in[4];
    const float* bk2 = (const float*)d_in[5];
    const float* Wq1 = (const float*)d_in[6];
    const float* bq1 = (const float*)d_in[7];
    const float* Wq2 = (const float*)d_in[8];
    const float* bq2 = (const float*)d_in[9];
    const float* Wvc = (const float*)d_in[10];
    const float* bvc = (const float*)d_in[11];
    const float* Wvp = (const float*)d_in[12];
    const float* bvp = (const float*)d_in[13];
    const float* Wg1 = (const float*)d_in[14];
    const float* bg1 = (const float*)d_in[15];
    const float* Wg2 = (const float*)d_in[16];
    const float* bg2 = (const float*)d_in[17];
    const float* lng = (const float*)d_in[18];
    const float* lnb = (const float*)d_in[19];
    const float* Wo  = (const float*)d_in[20];
    const float* bo  = (const float*)d_in[21];
    float* out = (float*)d_out;

    cudaFuncSetAttribute(k1_mma, cudaFuncAttributeMaxDynamicSharedMemorySize, 57344);

    cudaLaunchAttribute pdl;
    pdl.id = cudaLaunchAttributeProgrammaticStreamSerialization;
    pdl.val.programmaticStreamSerializationAllowed = 1;

    // k1: normal launch (no upstream dependency)
    k1_mma<<<dim3(32, 9), 256, 56064>>>(x, Wk1, bk1, Wq1, bq1, Wvc, bvc, Wvp, bvp, Wg1, bg1);

    {
        cudaLaunchConfig_t cfg = {};
        cfg.gridDim = dim3(128); cfg.blockDim = dim3(256);
        cfg.dynamicSmemBytes = 0; cfg.stream = (cudaStream_t)0;
        cfg.attrs = &pdl; cfg.numAttrs = 1;
        cudaLaunchKernelEx(&cfg, k23b_mma, Wk2, bk2, Wq2, bq2, Wg2, bg2, bp);
    }
    {
        cudaLaunchConfig_t cfg = {};
        cfg.gridDim = dim3(100); cfg.blockDim = dim3(256);
        cfg.dynamicSmemBytes = 0; cfg.stream = (cudaStream_t)0;
        cfg.attrs = &pdl; cfg.numAttrs = 1;
        cudaLaunchKernelEx(&cfg, k3a5_mma);
    }
    {
        cudaLaunchConfig_t cfg = {};
        cfg.gridDim = dim3(256); cfg.blockDim = dim3(256);
        cfg.dynamicSmemBytes = 0; cfg.stream = (cudaStream_t)0;
        cfg.attrs = &pdl; cfg.numAttrs = 1;
        cudaLaunchKernelEx(&cfg, k4_prefix);
    }
    {
        cudaLaunchConfig_t cfg = {};
        cfg.gridDim = dim3(32, 4); cfg.blockDim = dim3(256);
        cfg.dynamicSmemBytes = 0; cfg.stream = (cudaStream_t)0;
        cfg.attrs = &pdl; cfg.numAttrs = 1;
        cudaLaunchKernelEx(&cfg, k6_mma);
    }
    {
        cudaLaunchConfig_t cfg = {};
        cfg.gridDim = dim3(512); cfg.blockDim = dim3(256);
        cfg.dynamicSmemBytes = 0; cfg.stream = (cudaStream_t)0;
        cfg.attrs = &pdl; cfg.numAttrs = 1;
        cudaLaunchKernelEx(&cfg, k7_poscomb, lng, lnb);
    }
    {
        cudaLaunchConfig_t cfg = {};
        cfg.gridDim = dim3(32, 4); cfg.blockDim = dim3(256);
        cfg.dynamicSmemBytes = 0; cfg.stream = (cudaStream_t)0;
        cfg.attrs = &pdl; cfg.numAttrs = 1;
        cudaLaunchKernelEx(&cfg, k8_mma, x, Wo, bo, out);
    }
}